// round 4
// baseline (speedup 1.0000x reference)
#include <cuda_runtime.h>

// ---------------------------------------------------------------------------
// InstanceAdaptiveKeypointDetector2 — full-pipeline fp32 implementation.
// B=8, N=16384, C=256, K=16.  Output = [kp_pos (8,16,3) | y (8,16,256)].
// ---------------------------------------------------------------------------

static constexpr int Bc   = 8;
static constexpr int Nn   = 16384;
static constexpr int Cc   = 256;
static constexpr int Kc   = 16;
static constexpr int Mtot = Bc * Nn;          // 131072
#define EPSBN 1e-5f

// ------------------------------ scratch ------------------------------------
__device__ __align__(256) float g_x1[(size_t)Mtot * 256];
__device__ __align__(256) float g_x2[(size_t)Mtot * 256];
__device__ __align__(256) float g_x3[(size_t)Mtot * 512];
__device__ __align__(256) float g_off[(size_t)Mtot * 48];
__device__ __align__(256) float g_e[(size_t)Mtot * 16];
__device__ __align__(256) float g_sumxyz[Bc * 3];
__device__ __align__(256) float g_kpp[Bc * Kc * 3];
__device__ __align__(256) float g_spart[Bc * 64 * 16];
__device__ __align__(256) float g_S[Bc * Kc];
__device__ __align__(256) float g_fpart[(size_t)Bc * 4 * 16 * 16 * 64];
__device__ __align__(256) float g_kpf[Bc * Kc * 256];
__device__ __align__(256) float g_y1[Bc * Kc * 256];
__device__ __align__(256) float g_y2[Bc * Kc * 256];

// ------------------------- f32x2 packed helpers ----------------------------
__device__ __forceinline__ unsigned long long pk2(float lo, float hi) {
    unsigned long long r;
    asm("mov.b64 %0, {%1, %2};" : "=l"(r) : "f"(lo), "f"(hi));
    return r;
}
__device__ __forceinline__ void upk2(unsigned long long v, float& lo, float& hi) {
    asm("mov.b64 {%0, %1}, %2;" : "=f"(lo), "=f"(hi) : "l"(v));
}
// Blackwell packed fp32 FMA (FFMA2) — PTX-only, 2 MACs per issue.
__device__ __forceinline__ void ffma2(unsigned long long& c, unsigned long long a,
                                      unsigned long long b) {
    asm("fma.rn.f32x2 %0, %1, %2, %0;" : "+l"(c) : "l"(a), "l"(b));
}

// ------------------------------- SGEMM -------------------------------------
// C[m][d] = epilogue( sum_k A[m][k] * W[d][k] )
// A: M x Kd row-major.  W: D x Kd row-major.  C: M x D row-major.
// MODE 0: out = relu(z*s + t) with s,t folded from BN params (P0=g,P1=b,P2=m,P3=v)
// MODE 1: out = z + P0[d] (bias), with d < D store/load guards (D=48 case)
#define GBM 128
#define GBN 128
#define GBK 16

template <int MODE>
__global__ __launch_bounds__(256) void gemm_kernel(
    const float* __restrict__ A, const float* __restrict__ W,
    const float* __restrict__ P0, const float* __restrict__ P1,
    const float* __restrict__ P2, const float* __restrict__ P3,
    float* __restrict__ C, int M, int Kd, int D)
{
    __shared__ float As[2][GBK][GBM];
    __shared__ float Bs[2][GBK][GBN];

    const int tid = threadIdx.x;
    const int m0  = blockIdx.x * GBM;
    const int d0  = blockIdx.y * GBN;

    // Global-load mapping: each thread loads one float4 from rows lr and lr+64.
    const int lr = tid >> 2;
    const int lk = (tid & 3) * 4;

    const float* pA0 = A + (size_t)(m0 + lr) * Kd + lk;
    const float* pA1 = pA0 + (size_t)64 * Kd;
    const float* pB0 = W + (size_t)(d0 + lr) * Kd + lk;
    const float* pB1 = pB0 + (size_t)64 * Kd;
    const bool bv0 = (MODE == 0) || (d0 + lr < D);
    const bool bv1 = (MODE == 0) || (d0 + lr + 64 < D);

    // Compute mapping: 16x16 thread grid, 8x8 per thread (row-paired accumulators)
    const int tr = (tid >> 4) * 8;
    const int tc = (tid & 15) * 8;

    unsigned long long acc[4][8];
#pragma unroll
    for (int ip = 0; ip < 4; ++ip)
#pragma unroll
        for (int j = 0; j < 8; ++j) acc[ip][j] = 0ull;

    const float4 z4 = make_float4(0.f, 0.f, 0.f, 0.f);
    const int nk = Kd / GBK;

    // prologue: tile 0 -> buffer 0
    {
        float4 sa0 = *reinterpret_cast<const float4*>(pA0);
        float4 sa1 = *reinterpret_cast<const float4*>(pA1);
        float4 sb0 = bv0 ? *reinterpret_cast<const float4*>(pB0) : z4;
        float4 sb1 = bv1 ? *reinterpret_cast<const float4*>(pB1) : z4;
        const float* a0 = reinterpret_cast<const float*>(&sa0);
        const float* a1 = reinterpret_cast<const float*>(&sa1);
        const float* b0 = reinterpret_cast<const float*>(&sb0);
        const float* b1 = reinterpret_cast<const float*>(&sb1);
#pragma unroll
        for (int q = 0; q < 4; ++q) {
            As[0][lk + q][lr]      = a0[q];
            As[0][lk + q][lr + 64] = a1[q];
            Bs[0][lk + q][lr]      = b0[q];
            Bs[0][lk + q][lr + 64] = b1[q];
        }
    }
    __syncthreads();

    for (int t = 0; t < nk; ++t) {
        const int cur = t & 1;
        float4 sa0, sa1, sb0, sb1;
        if (t + 1 < nk) {
            const size_t kO = (size_t)(t + 1) * GBK;
            sa0 = *reinterpret_cast<const float4*>(pA0 + kO);
            sa1 = *reinterpret_cast<const float4*>(pA1 + kO);
            sb0 = bv0 ? *reinterpret_cast<const float4*>(pB0 + kO) : z4;
            sb1 = bv1 ? *reinterpret_cast<const float4*>(pB1 + kO) : z4;
        }

#pragma unroll
        for (int kk = 0; kk < GBK; ++kk) {
            ulonglong2 aA = *reinterpret_cast<const ulonglong2*>(&As[cur][kk][tr]);
            ulonglong2 aB = *reinterpret_cast<const ulonglong2*>(&As[cur][kk][tr + 4]);
            float4 bq0 = *reinterpret_cast<const float4*>(&Bs[cur][kk][tc]);
            float4 bq1 = *reinterpret_cast<const float4*>(&Bs[cur][kk][tc + 4]);
            unsigned long long ap0 = aA.x, ap1 = aA.y, ap2 = aB.x, ap3 = aB.y;
            float bvv[8] = {bq0.x, bq0.y, bq0.z, bq0.w, bq1.x, bq1.y, bq1.z, bq1.w};
#pragma unroll
            for (int j = 0; j < 8; ++j) {
                unsigned long long bd = pk2(bvv[j], bvv[j]);
                ffma2(acc[0][j], ap0, bd);
                ffma2(acc[1][j], ap1, bd);
                ffma2(acc[2][j], ap2, bd);
                ffma2(acc[3][j], ap3, bd);
            }
        }

        if (t + 1 < nk) {
            const int nb = (t + 1) & 1;
            const float* a0 = reinterpret_cast<const float*>(&sa0);
            const float* a1 = reinterpret_cast<const float*>(&sa1);
            const float* b0 = reinterpret_cast<const float*>(&sb0);
            const float* b1 = reinterpret_cast<const float*>(&sb1);
#pragma unroll
            for (int q = 0; q < 4; ++q) {
                As[nb][lk + q][lr]      = a0[q];
                As[nb][lk + q][lr + 64] = a1[q];
                Bs[nb][lk + q][lr]      = b0[q];
                Bs[nb][lk + q][lr + 64] = b1[q];
            }
        }
        __syncthreads();
    }

    // --------------------------- epilogue ---------------------------------
    if (MODE == 0) {
        float sc[8], tt[8];
#pragma unroll
        for (int j = 0; j < 8; ++j) {
            int d = d0 + tc + j;
            float s = P0[d] * rsqrtf(P3[d] + EPSBN);
            sc[j] = s;
            tt[j] = P1[d] - P2[d] * s;
        }
#pragma unroll
        for (int ip = 0; ip < 4; ++ip) {
            float lo[8], hi[8];
#pragma unroll
            for (int j = 0; j < 8; ++j) upk2(acc[ip][j], lo[j], hi[j]);
#pragma unroll
            for (int j = 0; j < 8; ++j) {
                lo[j] = fmaxf(lo[j] * sc[j] + tt[j], 0.f);
                hi[j] = fmaxf(hi[j] * sc[j] + tt[j], 0.f);
            }
            const int mA = m0 + tr + 2 * ip;
            float4* cA = reinterpret_cast<float4*>(C + (size_t)mA * D + d0 + tc);
            float4* cB = reinterpret_cast<float4*>(C + (size_t)(mA + 1) * D + d0 + tc);
            cA[0] = make_float4(lo[0], lo[1], lo[2], lo[3]);
            cA[1] = make_float4(lo[4], lo[5], lo[6], lo[7]);
            cB[0] = make_float4(hi[0], hi[1], hi[2], hi[3]);
            cB[1] = make_float4(hi[4], hi[5], hi[6], hi[7]);
        }
    } else {
#pragma unroll
        for (int ip = 0; ip < 4; ++ip) {
            float lo[8], hi[8];
#pragma unroll
            for (int j = 0; j < 8; ++j) upk2(acc[ip][j], lo[j], hi[j]);
            const int mA = m0 + tr + 2 * ip;
#pragma unroll
            for (int j = 0; j < 8; ++j) {
                int d = d0 + tc + j;
                if (d < D) {
                    float bias = P0[d];
                    C[(size_t)mA * D + d]       = lo[j] + bias;
                    C[(size_t)(mA + 1) * D + d] = hi[j] + bias;
                }
            }
        }
    }
}

// ------------------------- sum of xyz over points --------------------------
__global__ void sumxyz_kernel(const float* __restrict__ xyz, float* __restrict__ out) {
    const int b = blockIdx.x;
    const int tid = threadIdx.x;
    __shared__ float red[256][4];
    float s0 = 0.f, s1 = 0.f, s2 = 0.f;
    const float* p = xyz + (size_t)b * Nn * 3;
    for (int n = tid; n < Nn; n += 256) {
        s0 += p[n * 3 + 0];
        s1 += p[n * 3 + 1];
        s2 += p[n * 3 + 2];
    }
    red[tid][0] = s0; red[tid][1] = s1; red[tid][2] = s2;
    __syncthreads();
    for (int st = 128; st > 0; st >>= 1) {
        if (tid < st) {
            red[tid][0] += red[tid + st][0];
            red[tid][1] += red[tid + st][1];
            red[tid][2] += red[tid + st][2];
        }
        __syncthreads();
    }
    if (tid < 3) out[b * 3 + tid] = red[0][tid];
}

// ------------------------------ kp_pos -------------------------------------
__global__ void kppos_kernel(const float* __restrict__ off, const float* __restrict__ sxyz,
                             float* __restrict__ kpp, float* __restrict__ outp) {
    const int b = blockIdx.x >> 4;
    const int k = blockIdx.x & 15;
    const int tid = threadIdx.x;
    __shared__ float red[256][4];
    float s0 = 0.f, s1 = 0.f, s2 = 0.f;
    const float* p = off + (size_t)b * Nn * 48 + k * 3;
    for (int n = tid; n < Nn; n += 256) {
        size_t base = (size_t)n * 48;
        s0 += p[base + 0];
        s1 += p[base + 1];
        s2 += p[base + 2];
    }
    red[tid][0] = s0; red[tid][1] = s1; red[tid][2] = s2;
    __syncthreads();
    for (int st = 128; st > 0; st >>= 1) {
        if (tid < st) {
            red[tid][0] += red[tid + st][0];
            red[tid][1] += red[tid + st][1];
            red[tid][2] += red[tid + st][2];
        }
        __syncthreads();
    }
    if (tid < 3) {
        float v = (red[0][tid] + sxyz[b * 3 + tid]) * (1.f / (float)Nn);
        kpp[b * 48 + k * 3 + tid]  = v;
        outp[b * 48 + k * 3 + tid] = v;   // kp_pos is the first output
    }
}

// -------------------- exp(-dist) + per-block partial sums ------------------
__global__ __launch_bounds__(256) void expdist_kernel(
    const float* __restrict__ xyz, const float* __restrict__ off,
    const float* __restrict__ kpp, float* __restrict__ Eo, float* __restrict__ Spart)
{
    const int b = blockIdx.x >> 6;
    const int chunk = blockIdx.x & 63;
    const int tid = threadIdx.x;
    const int n = chunk * 256 + tid;
    const size_t gid = (size_t)b * Nn + n;

    __shared__ float kps[48];
    __shared__ float eS[256][17];
    if (tid < 48) kps[tid] = kpp[b * 48 + tid];
    __syncthreads();

    float4 ob4[12];
    const float4* op = reinterpret_cast<const float4*>(off + gid * 48);
#pragma unroll
    for (int i = 0; i < 12; ++i) ob4[i] = op[i];
    const float* ob = reinterpret_cast<const float*>(ob4);

    const float px = xyz[gid * 3 + 0];
    const float py = xyz[gid * 3 + 1];
    const float pz = xyz[gid * 3 + 2];

    float4 eb4[4];
    float* eb = reinterpret_cast<float*>(eb4);
#pragma unroll
    for (int k = 0; k < 16; ++k) {
        float vx = px + ob[3 * k + 0] - kps[3 * k + 0];
        float vy = py + ob[3 * k + 1] - kps[3 * k + 1];
        float vz = pz + ob[3 * k + 2] - kps[3 * k + 2];
        float e = expf(-sqrtf(vx * vx + vy * vy + vz * vz));
        eb[k] = e;
        eS[tid][k] = e;
    }
    float4* ew = reinterpret_cast<float4*>(Eo + gid * 16);
#pragma unroll
    for (int i = 0; i < 4; ++i) ew[i] = eb4[i];

    __syncthreads();
    for (int st = 128; st > 0; st >>= 1) {
        if (tid < st) {
#pragma unroll
            for (int k = 0; k < 16; ++k) eS[tid][k] += eS[tid + st][k];
        }
        __syncthreads();
    }
    if (tid < 16) Spart[(size_t)(b * 64 + chunk) * 16 + tid] = eS[0][tid];
}

// ------------------------ softmax denominators -----------------------------
__global__ void sreduce_kernel(const float* __restrict__ Spart, float* __restrict__ S) {
    const int t = threadIdx.x;          // 128 threads = (b,k)
    const int b = t >> 4, k = t & 15;
    float s = 0.f;
    for (int c = 0; c < 64; ++c) s += Spart[(size_t)(b * 64 + c) * 16 + k];
    S[t] = s;
}

// ------------------- keypoint feature pooling (partial) --------------------
__global__ __launch_bounds__(256) void kpfeat_partial_kernel(
    const float* __restrict__ F, const float* __restrict__ E, float* __restrict__ P)
{
    const int slab = blockIdx.x;   // 16 slabs of 1024 points
    const int cc   = blockIdx.y;   // 4 chunks of 64 channels
    const int b    = blockIdx.z;
    const int tid  = threadIdx.x;
    const int cl = tid & 63, kg = tid >> 6;

    __shared__ float Fs[16][64];
    __shared__ float es[16][17];
    float a0 = 0.f, a1 = 0.f, a2 = 0.f, a3 = 0.f;
    const int nbase = slab * 1024;

    for (int c0 = 0; c0 < 1024; c0 += 16) {
        __syncthreads();
#pragma unroll
        for (int r = 0; r < 4; ++r) {
            int j = r * 256 + tid;
            int nn = j >> 6, c = j & 63;
            Fs[nn][c] = F[(size_t)(b * Nn + nbase + c0 + nn) * 256 + cc * 64 + c];
        }
        {
            int nn = tid >> 4, kk = tid & 15;
            es[nn][kk] = E[(size_t)(b * Nn + nbase + c0 + nn) * 16 + kk];
        }
        __syncthreads();
#pragma unroll
        for (int nn = 0; nn < 16; ++nn) {
            float f = Fs[nn][cl];
            a0 += f * es[nn][kg * 4 + 0];
            a1 += f * es[nn][kg * 4 + 1];
            a2 += f * es[nn][kg * 4 + 2];
            a3 += f * es[nn][kg * 4 + 3];
        }
    }
    size_t base = ((size_t)(b * 4 + cc) * 16 + slab) * 16 * 64;
    P[base + (size_t)(kg * 4 + 0) * 64 + cl] = a0;
    P[base + (size_t)(kg * 4 + 1) * 64 + cl] = a1;
    P[base + (size_t)(kg * 4 + 2) * 64 + cl] = a2;
    P[base + (size_t)(kg * 4 + 3) * 64 + cl] = a3;
}

__global__ void kpfeat_reduce_kernel(const float* __restrict__ P, const float* __restrict__ S,
                                     float* __restrict__ KF) {
    const int b = blockIdx.x >> 4, k = blockIdx.x & 15;
    const int c = threadIdx.x;
    const int cc = c >> 6, cl = c & 63;
    float s = 0.f;
    for (int slab = 0; slab < 16; ++slab)
        s += P[(((size_t)(b * 4 + cc) * 16 + slab) * 16 + k) * 64 + cl];
    KF[(size_t)(b * 16 + k) * 256 + c] = s / S[b * 16 + k];
}

// ---------------------------- keypoint MLP ---------------------------------
// MODE 0: relu(bn(X @ W^T)).  MODE 1: plain X @ W^T (no bias).
template <int MODE>
__global__ __launch_bounds__(256) void mlp_kernel(
    const float* __restrict__ X, const float* __restrict__ W,
    const float* __restrict__ g, const float* __restrict__ bb,
    const float* __restrict__ mm, const float* __restrict__ vv,
    float* __restrict__ Out)
{
    const int d0 = blockIdx.x * 64;
    const int b  = blockIdx.y;
    const int tid = threadIdx.x;
    const int dl = tid & 63, kq = tid >> 6;

    __shared__ float Xs[16][256];
    __shared__ float Ws[64][65];

#pragma unroll
    for (int r = 0; r < 16; ++r) {
        int j = r * 256 + tid;
        (&Xs[0][0])[j] = X[(size_t)b * 16 * 256 + j];
    }

    float acc[4] = {0.f, 0.f, 0.f, 0.f};
    for (int c0 = 0; c0 < 256; c0 += 64) {
        __syncthreads();
#pragma unroll
        for (int r = 0; r < 16; ++r) {
            int j = r * 256 + tid;
            int dr = j >> 6, ccol = j & 63;
            Ws[dr][ccol] = W[(size_t)(d0 + dr) * 256 + c0 + ccol];
        }
        __syncthreads();
#pragma unroll 16
        for (int c = 0; c < 64; ++c) {
            float w = Ws[dl][c];
            acc[0] += Xs[kq + 0][c0 + c] * w;
            acc[1] += Xs[kq + 4][c0 + c] * w;
            acc[2] += Xs[kq + 8][c0 + c] * w;
            acc[3] += Xs[kq + 12][c0 + c] * w;
        }
    }

    const int d = d0 + dl;
    float s = 1.f, t = 0.f;
    if (MODE == 0) {
        s = g[d] * rsqrtf(vv[d] + EPSBN);
        t = bb[d] - mm[d] * s;
    }
#pragma unroll
    for (int r = 0; r < 4; ++r) {
        int k = kq + r * 4;
        float o = (MODE == 0) ? fmaxf(acc[r] * s + t, 0.f) : acc[r];
        Out[(size_t)(b * 16 + k) * 256 + d] = o;
    }
}

// ------------------------------ launcher -----------------------------------
extern "C" void kernel_launch(void* const* d_in, const int* in_sizes, int n_in,
                              void* d_out, int out_size) {
    const float* F   = (const float*)d_in[0];
    const float* xyz = (const float*)d_in[1];
    const float* W1  = (const float*)d_in[2];
    const float* g1  = (const float*)d_in[3];
    const float* b1  = (const float*)d_in[4];
    const float* m1  = (const float*)d_in[5];
    const float* v1  = (const float*)d_in[6];
    const float* W2  = (const float*)d_in[7];
    const float* g2  = (const float*)d_in[8];
    const float* b2  = (const float*)d_in[9];
    const float* m2  = (const float*)d_in[10];
    const float* v2  = (const float*)d_in[11];
    const float* W3  = (const float*)d_in[12];
    const float* g3  = (const float*)d_in[13];
    const float* b3  = (const float*)d_in[14];
    const float* m3  = (const float*)d_in[15];
    const float* v3  = (const float*)d_in[16];
    const float* Wo  = (const float*)d_in[17];
    const float* bo  = (const float*)d_in[18];
    const float* Wm1 = (const float*)d_in[19];
    const float* gm1 = (const float*)d_in[20];
    const float* bm1 = (const float*)d_in[21];
    const float* mm1 = (const float*)d_in[22];
    const float* vm1 = (const float*)d_in[23];
    const float* Wm2 = (const float*)d_in[24];
    const float* gm2 = (const float*)d_in[25];
    const float* bm2 = (const float*)d_in[26];
    const float* mm2 = (const float*)d_in[27];
    const float* vm2 = (const float*)d_in[28];
    const float* Wm3 = (const float*)d_in[29];
    float* out = (float*)d_out;

    float *x1, *x2, *x3, *off, *e, *sxyz, *kpp, *spart, *S, *fpart, *kpf, *y1, *y2;
    cudaGetSymbolAddress((void**)&x1, g_x1);
    cudaGetSymbolAddress((void**)&x2, g_x2);
    cudaGetSymbolAddress((void**)&x3, g_x3);
    cudaGetSymbolAddress((void**)&off, g_off);
    cudaGetSymbolAddress((void**)&e, g_e);
    cudaGetSymbolAddress((void**)&sxyz, g_sumxyz);
    cudaGetSymbolAddress((void**)&kpp, g_kpp);
    cudaGetSymbolAddress((void**)&spart, g_spart);
    cudaGetSymbolAddress((void**)&S, g_S);
    cudaGetSymbolAddress((void**)&fpart, g_fpart);
    cudaGetSymbolAddress((void**)&kpf, g_kpf);
    cudaGetSymbolAddress((void**)&y1, g_y1);
    cudaGetSymbolAddress((void**)&y2, g_y2);

    // backbone GEMM chain (BN+ReLU fused)
    gemm_kernel<0><<<dim3(Mtot / GBM, 2), 256>>>(F,  W1, g1, b1, m1, v1, x1, Mtot, 256, 256);
    gemm_kernel<0><<<dim3(Mtot / GBM, 2), 256>>>(x1, W2, g2, b2, m2, v2, x2, Mtot, 256, 256);
    gemm_kernel<0><<<dim3(Mtot / GBM, 4), 256>>>(x2, W3, g3, b3, m3, v3, x3, Mtot, 256, 512);
    gemm_kernel<1><<<dim3(Mtot / GBM, 1), 256>>>(x3, Wo, bo, nullptr, nullptr, nullptr,
                                                 off, Mtot, 512, 48);
    // keypoint positions (deterministic mean)
    sumxyz_kernel<<<Bc, 256>>>(xyz, sxyz);
    kppos_kernel<<<Bc * Kc, 256>>>(off, sxyz, kpp, out);
    // softmax weights
    expdist_kernel<<<Bc * 64, 256>>>(xyz, off, kpp, e, spart);
    sreduce_kernel<<<1, 128>>>(spart, S);
    // weighted feature pooling
    kpfeat_partial_kernel<<<dim3(16, 4, Bc), 256>>>(F, e, fpart);
    kpfeat_reduce_kernel<<<Bc * Kc, 256>>>(fpart, S, kpf);
    // keypoint MLP
    mlp_kernel<0><<<dim3(4, Bc), 256>>>(kpf, Wm1, gm1, bm1, mm1, vm1, y1);
    mlp_kernel<0><<<dim3(4, Bc), 256>>>(y1, Wm2, gm2, bm2, mm2, vm2, y2);
    mlp_kernel<1><<<dim3(4, Bc), 256>>>(y2, Wm3, nullptr, nullptr, nullptr, nullptr,
                                        out + Bc * Kc * 3);
}

// round 8
// speedup vs baseline: 1.4172x; 1.4172x over previous
#include <cuda_runtime.h>
#include <cstdint>

// ---------------------------------------------------------------------------
// InstanceAdaptiveKeypointDetector2 — split-tf32 mma.sync backbone + fp32 tail.
// Split-tf32: a·b = ah·bh + al·bh + ah·bl with ah = a&~0x1FFF, al = a-ah.
// Recovers ~fp32 accuracy (error ~2^-22) at 3x tensor cost; single-pass tf32
// measured 2.7e-3 on kp_pos (fails 1e-3 gate).
// B=8, N=16384, C=256, K=16.  Output = [kp_pos (8,16,3) | y (8,16,256)].
// ---------------------------------------------------------------------------

static constexpr int Bc   = 8;
static constexpr int Nn   = 16384;
static constexpr int Kc   = 16;
static constexpr int Mtot = Bc * Nn;          // 131072
#define EPSBN 1e-5f

// ------------------------------ scratch ------------------------------------
__device__ __align__(256) float g_x1[(size_t)Mtot * 256];
__device__ __align__(256) float g_x2[(size_t)Mtot * 256];
__device__ __align__(256) float g_x3[(size_t)Mtot * 512];
__device__ __align__(256) float g_off[(size_t)Mtot * 48];
__device__ __align__(256) float g_e[(size_t)Mtot * 16];
__device__ __align__(256) float g_sumxyz[Bc * 3];
__device__ __align__(256) float g_kpp[Bc * Kc * 3];
__device__ __align__(256) float g_spart[Bc * 64 * 16];
__device__ __align__(256) float g_S[Bc * Kc];
__device__ __align__(256) float g_fpart[(size_t)Bc * 4 * 16 * 16 * 64];
__device__ __align__(256) float g_kpf[Bc * Kc * 256];
__device__ __align__(256) float g_y1[Bc * Kc * 256];
__device__ __align__(256) float g_y2[Bc * Kc * 256];

// --------------------------- cp.async helpers ------------------------------
__device__ __forceinline__ uint32_t smem_u32(const void* p) {
    uint32_t a;
    asm("{ .reg .u64 t; cvta.to.shared.u64 t, %1; cvt.u32.u64 %0, t; }"
        : "=r"(a) : "l"(p));
    return a;
}
__device__ __forceinline__ void cp_async16(uint32_t dst, const float* src, int src_bytes) {
    asm volatile("cp.async.cg.shared.global [%0], [%1], 16, %2;"
                 :: "r"(dst), "l"(src), "r"(src_bytes));
}
__device__ __forceinline__ void cp_commit() {
    asm volatile("cp.async.commit_group;" ::: "memory");
}
template <int N>
__device__ __forceinline__ void cp_wait() {
    asm volatile("cp.async.wait_group %0;" :: "n"(N) : "memory");
}

// tf32 m16n8k8 mma (HW reads upper 19 bits of each f32 operand)
__device__ __forceinline__ void mma_tf32(float* c, const uint32_t* a, const uint32_t* b) {
    asm volatile(
        "mma.sync.aligned.m16n8k8.row.col.f32.tf32.tf32.f32 "
        "{%0,%1,%2,%3}, {%4,%5,%6,%7}, {%8,%9}, {%0,%1,%2,%3};"
        : "+f"(c[0]), "+f"(c[1]), "+f"(c[2]), "+f"(c[3])
        : "r"(a[0]), "r"(a[1]), "r"(a[2]), "r"(a[3]), "r"(b[0]), "r"(b[1]));
}

// split fp32 -> (hi = HW-visible tf32 bits, lo = exact residual)
__device__ __forceinline__ void split_tf32(uint32_t x, uint32_t& hi, uint32_t& lo) {
    hi = x & 0xFFFFE000u;
    lo = __float_as_uint(__uint_as_float(x) - __uint_as_float(hi));
}

// ----------------------- split-tf32 tensor-core GEMM -----------------------
// C[m][d] = epilogue( sum_k A[m][k] * W[d][k] )
// A: M x Kd row-major.  W: D x Kd row-major.  C: M x D row-major.
// Block tile 128x128, K-chunk 32, 8 warps (2x4), warp tile 64x32.
// MODE 0: relu(z*sc + tt), BN folded (P0=g,P1=b,P2=m,P3=v).
// MODE 1: z + P0[d] bias, with d<D guards (D=48 case).
static constexpr int TSTR      = 36;                 // smem row stride (floats)
static constexpr int TILE_FL   = 128 * TSTR;         // one operand tile
static constexpr int BUF_FL    = 2 * TILE_FL;        // A+B per stage
static constexpr int GSMEM_BYT = 2 * BUF_FL * 4;     // double-buffered: 73728 B

template <int MODE>
__global__ __launch_bounds__(256) void mma_gemm(
    const float* __restrict__ A, const float* __restrict__ W,
    const float* __restrict__ P0, const float* __restrict__ P1,
    const float* __restrict__ P2, const float* __restrict__ P3,
    float* __restrict__ C, int M, int Kd, int D)
{
    extern __shared__ __align__(16) float smf[];
    const uint32_t smb = smem_u32(smf);

    const int tid  = threadIdx.x;
    const int wid  = tid >> 5, lane = tid & 31;
    const int wm   = wid & 1;          // 2 warp rows
    const int wn   = wid >> 1;         // 4 warp cols
    const int gq   = lane >> 2;        // group id 0..7
    const int tq   = lane & 3;         // thread-in-group 0..3
    const int m0   = blockIdx.x * 128;
    const int d0   = blockIdx.y * 128;

    // ---------------- fold BN / bias into per-thread sc/tt -----------------
    float sc[4][2], tt[4][2];
#pragma unroll
    for (int nt = 0; nt < 4; ++nt)
#pragma unroll
        for (int j = 0; j < 2; ++j) {
            const int d = d0 + wn * 32 + nt * 8 + 2 * tq + j;
            if (MODE == 0) {
                float s = P0[d] * rsqrtf(P3[d] + EPSBN);
                sc[nt][j] = s;
                tt[nt][j] = P1[d] - P2[d] * s;
            } else {
                sc[nt][j] = 1.f;
                tt[nt][j] = (d < D) ? P0[d] : 0.f;
            }
        }

    float acc[4][4][4];
#pragma unroll
    for (int mt = 0; mt < 4; ++mt)
#pragma unroll
        for (int nt = 0; nt < 4; ++nt)
#pragma unroll
            for (int q = 0; q < 4; ++q) acc[mt][nt][q] = 0.f;

    const float* Ap = A + (size_t)m0 * Kd;
    const int nch = Kd / 32;

    // loader lambda: chunk ch -> stage buf
    auto issue = [&](int ch, int buf) {
        const int k0 = ch * 32;
        const uint32_t sa = smb + (uint32_t)(buf * BUF_FL) * 4u;
        const uint32_t sb = sa + (uint32_t)TILE_FL * 4u;
#pragma unroll
        for (int i = 0; i < 4; ++i) {                    // A: 128 x 32 (8 f4/row)
            const int idx = i * 256 + tid;
            const int r = idx >> 3, q = idx & 7;
            cp_async16(sa + (uint32_t)(r * TSTR + q * 4) * 4u,
                       Ap + (size_t)r * Kd + k0 + q * 4, 16);
        }
#pragma unroll
        for (int i = 0; i < 4; ++i) {                    // B: 128 x 32
            const int idx = i * 256 + tid;
            const int r = idx >> 3, q = idx & 7;
            int row = d0 + r;
            int vb  = (MODE == 0 || row < D) ? 16 : 0;
            int rs  = (MODE == 0 || row < D) ? row : 0;
            cp_async16(sb + (uint32_t)(r * TSTR + q * 4) * 4u,
                       W + (size_t)rs * Kd + k0 + q * 4, vb);
        }
        cp_commit();
    };

    issue(0, 0);
    if (nch > 1) issue(1, 1);

    for (int ch = 0; ch < nch; ++ch) {
        if (ch + 1 < nch) cp_wait<1>(); else cp_wait<0>();
        __syncthreads();

        const float* sA = smf + (ch & 1) * BUF_FL;
        const float* sB = sA + TILE_FL;
#pragma unroll
        for (int ks = 0; ks < 4; ++ks) {
            const int kk = ks * 8;
            uint32_t ah[4][4], al[4][4], bh[4][2], bl[4][2];
#pragma unroll
            for (int mt = 0; mt < 4; ++mt) {
                const int r = wm * 64 + mt * 16 + gq;
                uint32_t a0 = __float_as_uint(sA[r * TSTR + kk + tq]);
                uint32_t a1 = __float_as_uint(sA[(r + 8) * TSTR + kk + tq]);
                uint32_t a2 = __float_as_uint(sA[r * TSTR + kk + tq + 4]);
                uint32_t a3 = __float_as_uint(sA[(r + 8) * TSTR + kk + tq + 4]);
                split_tf32(a0, ah[mt][0], al[mt][0]);
                split_tf32(a1, ah[mt][1], al[mt][1]);
                split_tf32(a2, ah[mt][2], al[mt][2]);
                split_tf32(a3, ah[mt][3], al[mt][3]);
            }
#pragma unroll
            for (int nt = 0; nt < 4; ++nt) {
                const int n = wn * 32 + nt * 8 + gq;
                uint32_t b0 = __float_as_uint(sB[n * TSTR + kk + tq]);
                uint32_t b1 = __float_as_uint(sB[n * TSTR + kk + tq + 4]);
                split_tf32(b0, bh[nt][0], bl[nt][0]);
                split_tf32(b1, bh[nt][1], bl[nt][1]);
            }
#pragma unroll
            for (int mt = 0; mt < 4; ++mt)
#pragma unroll
                for (int nt = 0; nt < 4; ++nt) {
                    mma_tf32(acc[mt][nt], ah[mt], bh[nt]);   // main term
                    mma_tf32(acc[mt][nt], al[mt], bh[nt]);   // A residual
                    mma_tf32(acc[mt][nt], ah[mt], bl[nt]);   // B residual
                }
        }
        __syncthreads();
        if (ch + 2 < nch) issue(ch + 2, ch & 1);
    }

    // ------------------------------ epilogue -------------------------------
#pragma unroll
    for (int mt = 0; mt < 4; ++mt) {
        const int m = m0 + wm * 64 + mt * 16 + gq;
#pragma unroll
        for (int nt = 0; nt < 4; ++nt) {
            const int d = d0 + wn * 32 + nt * 8 + 2 * tq;
            float v0 = acc[mt][nt][0] * sc[nt][0] + tt[nt][0];
            float v1 = acc[mt][nt][1] * sc[nt][1] + tt[nt][1];
            float v2 = acc[mt][nt][2] * sc[nt][0] + tt[nt][0];
            float v3 = acc[mt][nt][3] * sc[nt][1] + tt[nt][1];
            if (MODE == 0) {
                v0 = fmaxf(v0, 0.f); v1 = fmaxf(v1, 0.f);
                v2 = fmaxf(v2, 0.f); v3 = fmaxf(v3, 0.f);
            }
            if (MODE == 0 || d < D) {
                *reinterpret_cast<float2*>(C + (size_t)m * D + d)       = make_float2(v0, v1);
                *reinterpret_cast<float2*>(C + (size_t)(m + 8) * D + d) = make_float2(v2, v3);
            }
        }
    }
}

// ------------------------- sum of xyz over points --------------------------
__global__ void sumxyz_kernel(const float* __restrict__ xyz, float* __restrict__ out) {
    const int b = blockIdx.x;
    const int tid = threadIdx.x;
    __shared__ float red[256][4];
    float s0 = 0.f, s1 = 0.f, s2 = 0.f;
    const float* p = xyz + (size_t)b * Nn * 3;
    for (int n = tid; n < Nn; n += 256) {
        s0 += p[n * 3 + 0];
        s1 += p[n * 3 + 1];
        s2 += p[n * 3 + 2];
    }
    red[tid][0] = s0; red[tid][1] = s1; red[tid][2] = s2;
    __syncthreads();
    for (int st = 128; st > 0; st >>= 1) {
        if (tid < st) {
            red[tid][0] += red[tid + st][0];
            red[tid][1] += red[tid + st][1];
            red[tid][2] += red[tid + st][2];
        }
        __syncthreads();
    }
    if (tid < 3) out[b * 3 + tid] = red[0][tid];
}

// ------------------------------ kp_pos -------------------------------------
__global__ void kppos_kernel(const float* __restrict__ off, const float* __restrict__ sxyz,
                             float* __restrict__ kpp, float* __restrict__ outp) {
    const int b = blockIdx.x >> 4;
    const int k = blockIdx.x & 15;
    const int tid = threadIdx.x;
    __shared__ float red[256][4];
    float s0 = 0.f, s1 = 0.f, s2 = 0.f;
    const float* p = off + (size_t)b * Nn * 48 + k * 3;
    for (int n = tid; n < Nn; n += 256) {
        size_t base = (size_t)n * 48;
        s0 += p[base + 0];
        s1 += p[base + 1];
        s2 += p[base + 2];
    }
    red[tid][0] = s0; red[tid][1] = s1; red[tid][2] = s2;
    __syncthreads();
    for (int st = 128; st > 0; st >>= 1) {
        if (tid < st) {
            red[tid][0] += red[tid + st][0];
            red[tid][1] += red[tid + st][1];
            red[tid][2] += red[tid + st][2];
        }
        __syncthreads();
    }
    if (tid < 3) {
        float v = (red[0][tid] + sxyz[b * 3 + tid]) * (1.f / (float)Nn);
        kpp[b * 48 + k * 3 + tid]  = v;
        outp[b * 48 + k * 3 + tid] = v;   // kp_pos is the first output
    }
}

// -------------------- exp(-dist) + per-block partial sums ------------------
__global__ __launch_bounds__(256) void expdist_kernel(
    const float* __restrict__ xyz, const float* __restrict__ off,
    const float* __restrict__ kpp, float* __restrict__ Eo, float* __restrict__ Spart)
{
    const int b = blockIdx.x >> 6;
    const int chunk = blockIdx.x & 63;
    const int tid = threadIdx.x;
    const int n = chunk * 256 + tid;
    const size_t gid = (size_t)b * Nn + n;

    __shared__ float kps[48];
    __shared__ float eS[256][17];
    if (tid < 48) kps[tid] = kpp[b * 48 + tid];
    __syncthreads();

    float4 ob4[12];
    const float4* op = reinterpret_cast<const float4*>(off + gid * 48);
#pragma unroll
    for (int i = 0; i < 12; ++i) ob4[i] = op[i];
    const float* ob = reinterpret_cast<const float*>(ob4);

    const float px = xyz[gid * 3 + 0];
    const float py = xyz[gid * 3 + 1];
    const float pz = xyz[gid * 3 + 2];

    float4 eb4[4];
    float* eb = reinterpret_cast<float*>(eb4);
#pragma unroll
    for (int k = 0; k < 16; ++k) {
        float vx = px + ob[3 * k + 0] - kps[3 * k + 0];
        float vy = py + ob[3 * k + 1] - kps[3 * k + 1];
        float vz = pz + ob[3 * k + 2] - kps[3 * k + 2];
        float e = expf(-sqrtf(vx * vx + vy * vy + vz * vz));
        eb[k] = e;
        eS[tid][k] = e;
    }
    float4* ew = reinterpret_cast<float4*>(Eo + gid * 16);
#pragma unroll
    for (int i = 0; i < 4; ++i) ew[i] = eb4[i];

    __syncthreads();
    for (int st = 128; st > 0; st >>= 1) {
        if (tid < st) {
#pragma unroll
            for (int k = 0; k < 16; ++k) eS[tid][k] += eS[tid + st][k];
        }
        __syncthreads();
    }
    if (tid < 16) Spart[(size_t)(b * 64 + chunk) * 16 + tid] = eS[0][tid];
}

// ------------------------ softmax denominators -----------------------------
__global__ void sreduce_kernel(const float* __restrict__ Spart, float* __restrict__ S) {
    const int t = threadIdx.x;          // 128 threads = (b,k)
    const int b = t >> 4, k = t & 15;
    float s = 0.f;
    for (int c = 0; c < 64; ++c) s += Spart[(size_t)(b * 64 + c) * 16 + k];
    S[t] = s;
}

// ------------------- keypoint feature pooling (partial) --------------------
__global__ __launch_bounds__(256) void kpfeat_partial_kernel(
    const float* __restrict__ F, const float* __restrict__ E, float* __restrict__ P)
{
    const int slab = blockIdx.x;   // 16 slabs of 1024 points
    const int cc   = blockIdx.y;   // 4 chunks of 64 channels
    const int b    = blockIdx.z;
    const int tid  = threadIdx.x;
    const int cl = tid & 63, kg = tid >> 6;

    __shared__ float Fs[16][64];
    __shared__ float es[16][17];
    float a0 = 0.f, a1 = 0.f, a2 = 0.f, a3 = 0.f;
    const int nbase = slab * 1024;

    for (int c0 = 0; c0 < 1024; c0 += 16) {
        __syncthreads();
#pragma unroll
        for (int r = 0; r < 4; ++r) {
            int j = r * 256 + tid;
            int nn = j >> 6, c = j & 63;
            Fs[nn][c] = F[(size_t)(b * Nn + nbase + c0 + nn) * 256 + cc * 64 + c];
        }
        {
            int nn = tid >> 4, kk = tid & 15;
            es[nn][kk] = E[(size_t)(b * Nn + nbase + c0 + nn) * 16 + kk];
        }
        __syncthreads();
#pragma unroll
        for (int nn = 0; nn < 16; ++nn) {
            float f = Fs[nn][cl];
            a0 += f * es[nn][kg * 4 + 0];
            a1 += f * es[nn][kg * 4 + 1];
            a2 += f * es[nn][kg * 4 + 2];
            a3 += f * es[nn][kg * 4 + 3];
        }
    }
    size_t base = ((size_t)(b * 4 + cc) * 16 + slab) * 16 * 64;
    P[base + (size_t)(kg * 4 + 0) * 64 + cl] = a0;
    P[base + (size_t)(kg * 4 + 1) * 64 + cl] = a1;
    P[base + (size_t)(kg * 4 + 2) * 64 + cl] = a2;
    P[base + (size_t)(kg * 4 + 3) * 64 + cl] = a3;
}

__global__ void kpfeat_reduce_kernel(const float* __restrict__ P, const float* __restrict__ S,
                                     float* __restrict__ KF) {
    const int b = blockIdx.x >> 4, k = blockIdx.x & 15;
    const int c = threadIdx.x;
    const int cc = c >> 6, cl = c & 63;
    float s = 0.f;
    for (int slab = 0; slab < 16; ++slab)
        s += P[(((size_t)(b * 4 + cc) * 16 + slab) * 16 + k) * 64 + cl];
    KF[(size_t)(b * 16 + k) * 256 + c] = s / S[b * 16 + k];
}

// ---------------------------- keypoint MLP ---------------------------------
// MODE 0: relu(bn(X @ W^T)).  MODE 1: plain X @ W^T (no bias).
template <int MODE>
__global__ __launch_bounds__(256) void mlp_kernel(
    const float* __restrict__ X, const float* __restrict__ W,
    const float* __restrict__ g, const float* __restrict__ bb,
    const float* __restrict__ mm, const float* __restrict__ vv,
    float* __restrict__ Out)
{
    const int d0 = blockIdx.x * 64;
    const int b  = blockIdx.y;
    const int tid = threadIdx.x;
    const int dl = tid & 63, kq = tid >> 6;

    __shared__ float Xs[16][256];
    __shared__ float Ws[64][65];

#pragma unroll
    for (int r = 0; r < 16; ++r) {
        int j = r * 256 + tid;
        (&Xs[0][0])[j] = X[(size_t)b * 16 * 256 + j];
    }

    float acc[4] = {0.f, 0.f, 0.f, 0.f};
    for (int c0 = 0; c0 < 256; c0 += 64) {
        __syncthreads();
#pragma unroll
        for (int r = 0; r < 16; ++r) {
            int j = r * 256 + tid;
            int dr = j >> 6, ccol = j & 63;
            Ws[dr][ccol] = W[(size_t)(d0 + dr) * 256 + c0 + ccol];
        }
        __syncthreads();
#pragma unroll 16
        for (int c = 0; c < 64; ++c) {
            float w = Ws[dl][c];
            acc[0] += Xs[kq + 0][c0 + c] * w;
            acc[1] += Xs[kq + 4][c0 + c] * w;
            acc[2] += Xs[kq + 8][c0 + c] * w;
            acc[3] += Xs[kq + 12][c0 + c] * w;
        }
    }

    const int d = d0 + dl;
    float s = 1.f, t = 0.f;
    if (MODE == 0) {
        s = g[d] * rsqrtf(vv[d] + EPSBN);
        t = bb[d] - mm[d] * s;
    }
#pragma unroll
    for (int r = 0; r < 4; ++r) {
        int k = kq + r * 4;
        float o = (MODE == 0) ? fmaxf(acc[r] * s + t, 0.f) : acc[r];
        Out[(size_t)(b * 16 + k) * 256 + d] = o;
    }
}

// ------------------------------ launcher -----------------------------------
extern "C" void kernel_launch(void* const* d_in, const int* in_sizes, int n_in,
                              void* d_out, int out_size) {
    const float* F   = (const float*)d_in[0];
    const float* xyz = (const float*)d_in[1];
    const float* W1  = (const float*)d_in[2];
    const float* g1  = (const float*)d_in[3];
    const float* b1  = (const float*)d_in[4];
    const float* m1  = (const float*)d_in[5];
    const float* v1  = (const float*)d_in[6];
    const float* W2  = (const float*)d_in[7];
    const float* g2  = (const float*)d_in[8];
    const float* b2  = (const float*)d_in[9];
    const float* m2  = (const float*)d_in[10];
    const float* v2  = (const float*)d_in[11];
    const float* W3  = (const float*)d_in[12];
    const float* g3  = (const float*)d_in[13];
    const float* b3  = (const float*)d_in[14];
    const float* m3  = (const float*)d_in[15];
    const float* v3  = (const float*)d_in[16];
    const float* Wo  = (const float*)d_in[17];
    const float* bo  = (const float*)d_in[18];
    const float* Wm1 = (const float*)d_in[19];
    const float* gm1 = (const float*)d_in[20];
    const float* bm1 = (const float*)d_in[21];
    const float* mm1 = (const float*)d_in[22];
    const float* vm1 = (const float*)d_in[23];
    const float* Wm2 = (const float*)d_in[24];
    const float* gm2 = (const float*)d_in[25];
    const float* bm2 = (const float*)d_in[26];
    const float* mm2 = (const float*)d_in[27];
    const float* vm2 = (const float*)d_in[28];
    const float* Wm3 = (const float*)d_in[29];
    float* out = (float*)d_out;

    float *x1, *x2, *x3, *off, *e, *sxyz, *kpp, *spart, *S, *fpart, *kpf, *y1, *y2;
    cudaGetSymbolAddress((void**)&x1, g_x1);
    cudaGetSymbolAddress((void**)&x2, g_x2);
    cudaGetSymbolAddress((void**)&x3, g_x3);
    cudaGetSymbolAddress((void**)&off, g_off);
    cudaGetSymbolAddress((void**)&e, g_e);
    cudaGetSymbolAddress((void**)&sxyz, g_sumxyz);
    cudaGetSymbolAddress((void**)&kpp, g_kpp);
    cudaGetSymbolAddress((void**)&spart, g_spart);
    cudaGetSymbolAddress((void**)&S, g_S);
    cudaGetSymbolAddress((void**)&fpart, g_fpart);
    cudaGetSymbolAddress((void**)&kpf, g_kpf);
    cudaGetSymbolAddress((void**)&y1, g_y1);
    cudaGetSymbolAddress((void**)&y2, g_y2);

    // raise dynamic-smem limit (not a stream op; safe under graph capture,
    // called unconditionally — no static guards)
    cudaFuncSetAttribute(mma_gemm<0>, cudaFuncAttributeMaxDynamicSharedMemorySize, GSMEM_BYT);
    cudaFuncSetAttribute(mma_gemm<1>, cudaFuncAttributeMaxDynamicSharedMemorySize, GSMEM_BYT);

    // backbone GEMM chain on split-tf32 tensor cores (BN+ReLU / bias fused)
    mma_gemm<0><<<dim3(Mtot / 128, 2), 256, GSMEM_BYT>>>(F,  W1, g1, b1, m1, v1, x1, Mtot, 256, 256);
    mma_gemm<0><<<dim3(Mtot / 128, 2), 256, GSMEM_BYT>>>(x1, W2, g2, b2, m2, v2, x2, Mtot, 256, 256);
    mma_gemm<0><<<dim3(Mtot / 128, 4), 256, GSMEM_BYT>>>(x2, W3, g3, b3, m3, v3, x3, Mtot, 256, 512);
    mma_gemm<1><<<dim3(Mtot / 128, 1), 256, GSMEM_BYT>>>(x3, Wo, bo, nullptr, nullptr, nullptr,
                                                         off, Mtot, 512, 48);
    // keypoint positions (deterministic mean)
    sumxyz_kernel<<<Bc, 256>>>(xyz, sxyz);
    kppos_kernel<<<Bc * Kc, 256>>>(off, sxyz, kpp, out);
    // softmax weights
    expdist_kernel<<<Bc * 64, 256>>>(xyz, off, kpp, e, spart);
    sreduce_kernel<<<1, 128>>>(spart, S);
    // weighted feature pooling
    kpfeat_partial_kernel<<<dim3(16, 4, Bc), 256>>>(F, e, fpart);
    kpfeat_reduce_kernel<<<Bc * Kc, 256>>>(fpart, S, kpf);
    // keypoint MLP (fp32 — tiny, keeps precision headroom)
    mlp_kernel<0><<<dim3(4, Bc), 256>>>(kpf, Wm1, gm1, bm1, mm1, vm1, y1);
    mlp_kernel<0><<<dim3(4, Bc), 256>>>(y1, Wm2, gm2, bm2, mm2, vm2, y2);
    mlp_kernel<1><<<dim3(4, Bc), 256>>>(y2, Wm3, nullptr, nullptr, nullptr, nullptr,
                                        out + Bc * Kc * 3);
}

// round 9
// speedup vs baseline: 2.0579x; 1.4521x over previous
#include <cuda_runtime.h>
#include <cstdint>

// ---------------------------------------------------------------------------
// InstanceAdaptiveKeypointDetector2 — bf16x3 mma.sync backbone + fp32 tail.
// bf16x3: a·b = ah·bh + al·bh + ah·bl with ah = bf16rn(a), al = bf16rn(a-ah).
// Per-product error ~2^-18 -> chain rel_err ~2-5e-5 (gate 1e-3).
// m16n8k16 bf16 does 2x the K of m16n8k8 tf32 per instruction -> ~2x tensor tput.
// B=8, N=16384, C=256, K=16.  Output = [kp_pos (8,16,3) | y (8,16,256)].
// ---------------------------------------------------------------------------

static constexpr int Bc   = 8;
static constexpr int Nn   = 16384;
static constexpr int Kc   = 16;
static constexpr int Mtot = Bc * Nn;          // 131072
#define EPSBN 1e-5f

// ------------------------------ scratch ------------------------------------
__device__ __align__(256) float g_x1[(size_t)Mtot * 256];
__device__ __align__(256) float g_x2[(size_t)Mtot * 256];
__device__ __align__(256) float g_x3[(size_t)Mtot * 512];
__device__ __align__(256) float g_off[(size_t)Mtot * 48];
__device__ __align__(256) float g_e[(size_t)Mtot * 16];
__device__ __align__(256) float g_sumxyz[Bc * 3];
__device__ __align__(256) float g_kpp[Bc * Kc * 3];
__device__ __align__(256) float g_spart[Bc * 64 * 16];
__device__ __align__(256) float g_S[Bc * Kc];
__device__ __align__(256) float g_fpart[(size_t)Bc * 4 * 16 * 16 * 64];
__device__ __align__(256) float g_kpf[Bc * Kc * 256];
__device__ __align__(256) float g_y1[Bc * Kc * 256];
__device__ __align__(256) float g_y2[Bc * Kc * 256];

// --------------------------- cp.async helpers ------------------------------
__device__ __forceinline__ uint32_t smem_u32(const void* p) {
    uint32_t a;
    asm("{ .reg .u64 t; cvta.to.shared.u64 t, %1; cvt.u32.u64 %0, t; }"
        : "=r"(a) : "l"(p));
    return a;
}
__device__ __forceinline__ void cp_async16(uint32_t dst, const float* src, int src_bytes) {
    asm volatile("cp.async.cg.shared.global [%0], [%1], 16, %2;"
                 :: "r"(dst), "l"(src), "r"(src_bytes));
}
__device__ __forceinline__ void cp_commit() {
    asm volatile("cp.async.commit_group;" ::: "memory");
}
template <int N>
__device__ __forceinline__ void cp_wait() {
    asm volatile("cp.async.wait_group %0;" :: "n"(N) : "memory");
}

// bf16 m16n8k16 mma, fp32 accumulate
__device__ __forceinline__ void mma_bf16(float* c, const uint32_t* a, const uint32_t* b) {
    asm volatile(
        "mma.sync.aligned.m16n8k16.row.col.f32.bf16.bf16.f32 "
        "{%0,%1,%2,%3}, {%4,%5,%6,%7}, {%8,%9}, {%0,%1,%2,%3};"
        : "+f"(c[0]), "+f"(c[1]), "+f"(c[2]), "+f"(c[3])
        : "r"(a[0]), "r"(a[1]), "r"(a[2]), "r"(a[3]), "r"(b[0]), "r"(b[1]));
}

// split consecutive fp32 pair (p.x=k even, p.y=k+1) into bf16x2 hi + residual lo
__device__ __forceinline__ void split_bf(float2 p, uint32_t& hi, uint32_t& lo) {
    asm("cvt.rn.bf16x2.f32 %0, %1, %2;" : "=r"(hi) : "f"(p.y), "f"(p.x));
    float h0 = __uint_as_float(hi << 16);           // bf16->f32 of low half
    float h1 = __uint_as_float(hi & 0xFFFF0000u);   // bf16->f32 of high half
    asm("cvt.rn.bf16x2.f32 %0, %1, %2;" : "=r"(lo) : "f"(p.y - h1), "f"(p.x - h0));
}

// ----------------------- bf16x3 tensor-core GEMM ---------------------------
// C[m][d] = epilogue( sum_k A[m][k] * W[d][k] )
// A: M x Kd row-major.  W: D x Kd row-major.  C: M x D row-major.
// Block tile 128 x NT, K-chunk 32 (2 x k16 steps), 8 warps (2 x 4),
// warp tile 64 x NT/4.
// MODE 0: relu(z*sc + tt), BN folded (P0=g,P1=b,P2=m,P3=v).
// MODE 1: z + P0[d] bias, with d<D guards (D=48, NT=64 case).
static constexpr int TSTR = 40;                  // smem row stride (floats); 40%32=8
                                                 // -> conflict-free LDS.64 frags

template <int MODE, int NT>
__global__ __launch_bounds__(256) void mma_gemm(
    const float* __restrict__ A, const float* __restrict__ W,
    const float* __restrict__ P0, const float* __restrict__ P1,
    const float* __restrict__ P2, const float* __restrict__ P3,
    float* __restrict__ C, int M, int Kd, int D)
{
    constexpr int NTW    = NT / 4;               // warp n-tile
    constexpr int NTC    = NT / 32;              // nt iterations (8-wide each)
    constexpr int TILE_A = 128 * TSTR;
    constexpr int TILE_B = NT * TSTR;
    constexpr int BUF_FL = TILE_A + TILE_B;

    extern __shared__ __align__(16) float smf[];
    const uint32_t smb = smem_u32(smf);

    const int tid  = threadIdx.x;
    const int wid  = tid >> 5, lane = tid & 31;
    const int wm   = wid & 1;          // 2 warp rows
    const int wn   = wid >> 1;         // 4 warp cols
    const int gq   = lane >> 2;        // group id 0..7
    const int tq   = lane & 3;         // thread-in-group 0..3
    const int m0   = blockIdx.x * 128;
    const int d0   = blockIdx.y * NT;

    // ---------------- fold BN / bias into per-thread sc/tt -----------------
    float sc[NTC][2], tt[NTC][2];
#pragma unroll
    for (int nt = 0; nt < NTC; ++nt)
#pragma unroll
        for (int j = 0; j < 2; ++j) {
            const int d = d0 + wn * NTW + nt * 8 + 2 * tq + j;
            if (MODE == 0) {
                float s = P0[d] * rsqrtf(P3[d] + EPSBN);
                sc[nt][j] = s;
                tt[nt][j] = P1[d] - P2[d] * s;
            } else {
                sc[nt][j] = 1.f;
                tt[nt][j] = (d < D) ? P0[d] : 0.f;
            }
        }

    float acc[4][NTC][4];
#pragma unroll
    for (int mt = 0; mt < 4; ++mt)
#pragma unroll
        for (int nt = 0; nt < NTC; ++nt)
#pragma unroll
            for (int q = 0; q < 4; ++q) acc[mt][nt][q] = 0.f;

    const float* Ap = A + (size_t)m0 * Kd;
    const int nch = Kd / 32;

    // loader: chunk ch -> stage buf (cp.async, fp32 in smem)
    auto issue = [&](int ch, int buf) {
        const int k0 = ch * 32;
        const uint32_t sa = smb + (uint32_t)(buf * BUF_FL) * 4u;
        const uint32_t sb = sa + (uint32_t)TILE_A * 4u;
#pragma unroll
        for (int i = 0; i < 4; ++i) {                    // A: 128 rows x 8 float4
            const int idx = i * 256 + tid;
            const int r = idx >> 3, q = idx & 7;
            cp_async16(sa + (uint32_t)(r * TSTR + q * 4) * 4u,
                       Ap + (size_t)r * Kd + k0 + q * 4, 16);
        }
#pragma unroll
        for (int i = 0; i < NT / 32; ++i) {              // B: NT rows x 8 float4
            const int idx = i * 256 + tid;
            const int r = idx >> 3, q = idx & 7;
            int row = d0 + r;
            int vb  = (MODE == 0 || row < D) ? 16 : 0;   // zero-fill pad rows
            int rs  = (MODE == 0 || row < D) ? row : 0;
            cp_async16(sb + (uint32_t)(r * TSTR + q * 4) * 4u,
                       W + (size_t)rs * Kd + k0 + q * 4, vb);
        }
        cp_commit();
    };

    issue(0, 0);
    if (nch > 1) issue(1, 1);

    for (int ch = 0; ch < nch; ++ch) {
        if (ch + 1 < nch) cp_wait<1>(); else cp_wait<0>();
        __syncthreads();

        const float* sA = smf + (ch & 1) * BUF_FL;
        const float* sB = sA + TILE_A;
#pragma unroll
        for (int ks = 0; ks < 2; ++ks) {                 // 2 x k16 per 32-chunk
            const int kk = ks * 16;
            uint32_t ah[4][4], al[4][4], bh[NTC][2], bl[NTC][2];
#pragma unroll
            for (int mt = 0; mt < 4; ++mt) {
                const int r = wm * 64 + mt * 16 + gq;
                float2 p00 = *reinterpret_cast<const float2*>(&sA[r * TSTR + kk + 2 * tq]);
                float2 p10 = *reinterpret_cast<const float2*>(&sA[(r + 8) * TSTR + kk + 2 * tq]);
                float2 p01 = *reinterpret_cast<const float2*>(&sA[r * TSTR + kk + 2 * tq + 8]);
                float2 p11 = *reinterpret_cast<const float2*>(&sA[(r + 8) * TSTR + kk + 2 * tq + 8]);
                split_bf(p00, ah[mt][0], al[mt][0]);
                split_bf(p10, ah[mt][1], al[mt][1]);
                split_bf(p01, ah[mt][2], al[mt][2]);
                split_bf(p11, ah[mt][3], al[mt][3]);
            }
#pragma unroll
            for (int nt = 0; nt < NTC; ++nt) {
                const int n = wn * NTW + nt * 8 + gq;
                float2 q0 = *reinterpret_cast<const float2*>(&sB[n * TSTR + kk + 2 * tq]);
                float2 q1 = *reinterpret_cast<const float2*>(&sB[n * TSTR + kk + 2 * tq + 8]);
                split_bf(q0, bh[nt][0], bl[nt][0]);
                split_bf(q1, bh[nt][1], bl[nt][1]);
            }
#pragma unroll
            for (int mt = 0; mt < 4; ++mt)
#pragma unroll
                for (int nt = 0; nt < NTC; ++nt) {
                    mma_bf16(acc[mt][nt], ah[mt], bh[nt]);   // main
                    mma_bf16(acc[mt][nt], al[mt], bh[nt]);   // A residual
                    mma_bf16(acc[mt][nt], ah[mt], bl[nt]);   // B residual
                }
        }
        __syncthreads();
        if (ch + 2 < nch) issue(ch + 2, ch & 1);
    }

    // ------------------------------ epilogue -------------------------------
#pragma unroll
    for (int mt = 0; mt < 4; ++mt) {
        const int m = m0 + wm * 64 + mt * 16 + gq;
#pragma unroll
        for (int nt = 0; nt < NTC; ++nt) {
            const int d = d0 + wn * NTW + nt * 8 + 2 * tq;
            float v0 = acc[mt][nt][0] * sc[nt][0] + tt[nt][0];
            float v1 = acc[mt][nt][1] * sc[nt][1] + tt[nt][1];
            float v2 = acc[mt][nt][2] * sc[nt][0] + tt[nt][0];
            float v3 = acc[mt][nt][3] * sc[nt][1] + tt[nt][1];
            if (MODE == 0) {
                v0 = fmaxf(v0, 0.f); v1 = fmaxf(v1, 0.f);
                v2 = fmaxf(v2, 0.f); v3 = fmaxf(v3, 0.f);
            }
            if (MODE == 0 || d < D) {
                *reinterpret_cast<float2*>(C + (size_t)m * D + d)       = make_float2(v0, v1);
                *reinterpret_cast<float2*>(C + (size_t)(m + 8) * D + d) = make_float2(v2, v3);
            }
        }
    }
}

// ------------------------- sum of xyz over points --------------------------
__global__ void sumxyz_kernel(const float* __restrict__ xyz, float* __restrict__ out) {
    const int b = blockIdx.x;
    const int tid = threadIdx.x;
    __shared__ float red[256][4];
    float s0 = 0.f, s1 = 0.f, s2 = 0.f;
    const float* p = xyz + (size_t)b * Nn * 3;
    for (int n = tid; n < Nn; n += 256) {
        s0 += p[n * 3 + 0];
        s1 += p[n * 3 + 1];
        s2 += p[n * 3 + 2];
    }
    red[tid][0] = s0; red[tid][1] = s1; red[tid][2] = s2;
    __syncthreads();
    for (int st = 128; st > 0; st >>= 1) {
        if (tid < st) {
            red[tid][0] += red[tid + st][0];
            red[tid][1] += red[tid + st][1];
            red[tid][2] += red[tid + st][2];
        }
        __syncthreads();
    }
    if (tid < 3) out[b * 3 + tid] = red[0][tid];
}

// ------------------------------ kp_pos -------------------------------------
__global__ void kppos_kernel(const float* __restrict__ off, const float* __restrict__ sxyz,
                             float* __restrict__ kpp, float* __restrict__ outp) {
    const int b = blockIdx.x >> 4;
    const int k = blockIdx.x & 15;
    const int tid = threadIdx.x;
    __shared__ float red[256][4];
    float s0 = 0.f, s1 = 0.f, s2 = 0.f;
    const float* p = off + (size_t)b * Nn * 48 + k * 3;
    for (int n = tid; n < Nn; n += 256) {
        size_t base = (size_t)n * 48;
        s0 += p[base + 0];
        s1 += p[base + 1];
        s2 += p[base + 2];
    }
    red[tid][0] = s0; red[tid][1] = s1; red[tid][2] = s2;
    __syncthreads();
    for (int st = 128; st > 0; st >>= 1) {
        if (tid < st) {
            red[tid][0] += red[tid + st][0];
            red[tid][1] += red[tid + st][1];
            red[tid][2] += red[tid + st][2];
        }
        __syncthreads();
    }
    if (tid < 3) {
        float v = (red[0][tid] + sxyz[b * 3 + tid]) * (1.f / (float)Nn);
        kpp[b * 48 + k * 3 + tid]  = v;
        outp[b * 48 + k * 3 + tid] = v;   // kp_pos is the first output
    }
}

// -------------------- exp(-dist) + per-block partial sums ------------------
__global__ __launch_bounds__(256) void expdist_kernel(
    const float* __restrict__ xyz, const float* __restrict__ off,
    const float* __restrict__ kpp, float* __restrict__ Eo, float* __restrict__ Spart)
{
    const int b = blockIdx.x >> 6;
    const int chunk = blockIdx.x & 63;
    const int tid = threadIdx.x;
    const int n = chunk * 256 + tid;
    const size_t gid = (size_t)b * Nn + n;

    __shared__ float kps[48];
    __shared__ float eS[256][17];
    if (tid < 48) kps[tid] = kpp[b * 48 + tid];
    __syncthreads();

    float4 ob4[12];
    const float4* op = reinterpret_cast<const float4*>(off + gid * 48);
#pragma unroll
    for (int i = 0; i < 12; ++i) ob4[i] = op[i];
    const float* ob = reinterpret_cast<const float*>(ob4);

    const float px = xyz[gid * 3 + 0];
    const float py = xyz[gid * 3 + 1];
    const float pz = xyz[gid * 3 + 2];

    float4 eb4[4];
    float* eb = reinterpret_cast<float*>(eb4);
#pragma unroll
    for (int k = 0; k < 16; ++k) {
        float vx = px + ob[3 * k + 0] - kps[3 * k + 0];
        float vy = py + ob[3 * k + 1] - kps[3 * k + 1];
        float vz = pz + ob[3 * k + 2] - kps[3 * k + 2];
        float e = expf(-sqrtf(vx * vx + vy * vy + vz * vz));
        eb[k] = e;
        eS[tid][k] = e;
    }
    float4* ew = reinterpret_cast<float4*>(Eo + gid * 16);
#pragma unroll
    for (int i = 0; i < 4; ++i) ew[i] = eb4[i];

    __syncthreads();
    for (int st = 128; st > 0; st >>= 1) {
        if (tid < st) {
#pragma unroll
            for (int k = 0; k < 16; ++k) eS[tid][k] += eS[tid + st][k];
        }
        __syncthreads();
    }
    if (tid < 16) Spart[(size_t)(b * 64 + chunk) * 16 + tid] = eS[0][tid];
}

// ------------------------ softmax denominators -----------------------------
__global__ void sreduce_kernel(const float* __restrict__ Spart, float* __restrict__ S) {
    const int t = threadIdx.x;          // 128 threads = (b,k)
    const int b = t >> 4, k = t & 15;
    float s = 0.f;
    for (int c = 0; c < 64; ++c) s += Spart[(size_t)(b * 64 + c) * 16 + k];
    S[t] = s;
}

// ------------------- keypoint feature pooling (partial) --------------------
__global__ __launch_bounds__(256) void kpfeat_partial_kernel(
    const float* __restrict__ F, const float* __restrict__ E, float* __restrict__ P)
{
    const int slab = blockIdx.x;   // 16 slabs of 1024 points
    const int cc   = blockIdx.y;   // 4 chunks of 64 channels
    const int b    = blockIdx.z;
    const int tid  = threadIdx.x;
    const int cl = tid & 63, kg = tid >> 6;

    __shared__ float Fs[16][64];
    __shared__ float es[16][17];
    float a0 = 0.f, a1 = 0.f, a2 = 0.f, a3 = 0.f;
    const int nbase = slab * 1024;

    for (int c0 = 0; c0 < 1024; c0 += 16) {
        __syncthreads();
#pragma unroll
        for (int r = 0; r < 4; ++r) {
            int j = r * 256 + tid;
            int nn = j >> 6, c = j & 63;
            Fs[nn][c] = F[(size_t)(b * Nn + nbase + c0 + nn) * 256 + cc * 64 + c];
        }
        {
            int nn = tid >> 4, kk = tid & 15;
            es[nn][kk] = E[(size_t)(b * Nn + nbase + c0 + nn) * 16 + kk];
        }
        __syncthreads();
#pragma unroll
        for (int nn = 0; nn < 16; ++nn) {
            float f = Fs[nn][cl];
            a0 += f * es[nn][kg * 4 + 0];
            a1 += f * es[nn][kg * 4 + 1];
            a2 += f * es[nn][kg * 4 + 2];
            a3 += f * es[nn][kg * 4 + 3];
        }
    }
    size_t base = ((size_t)(b * 4 + cc) * 16 + slab) * 16 * 64;
    P[base + (size_t)(kg * 4 + 0) * 64 + cl] = a0;
    P[base + (size_t)(kg * 4 + 1) * 64 + cl] = a1;
    P[base + (size_t)(kg * 4 + 2) * 64 + cl] = a2;
    P[base + (size_t)(kg * 4 + 3) * 64 + cl] = a3;
}

__global__ void kpfeat_reduce_kernel(const float* __restrict__ P, const float* __restrict__ S,
                                     float* __restrict__ KF) {
    const int b = blockIdx.x >> 4, k = blockIdx.x & 15;
    const int c = threadIdx.x;
    const int cc = c >> 6, cl = c & 63;
    float s = 0.f;
    for (int slab = 0; slab < 16; ++slab)
        s += P[(((size_t)(b * 4 + cc) * 16 + slab) * 16 + k) * 64 + cl];
    KF[(size_t)(b * 16 + k) * 256 + c] = s / S[b * 16 + k];
}

// ---------------------------- keypoint MLP ---------------------------------
// MODE 0: relu(bn(X @ W^T)).  MODE 1: plain X @ W^T (no bias).
template <int MODE>
__global__ __launch_bounds__(256) void mlp_kernel(
    const float* __restrict__ X, const float* __restrict__ W,
    const float* __restrict__ g, const float* __restrict__ bb,
    const float* __restrict__ mm, const float* __restrict__ vv,
    float* __restrict__ Out)
{
    const int d0 = blockIdx.x * 64;
    const int b  = blockIdx.y;
    const int tid = threadIdx.x;
    const int dl = tid & 63, kq = tid >> 6;

    __shared__ float Xs[16][256];
    __shared__ float Ws[64][65];

#pragma unroll
    for (int r = 0; r < 16; ++r) {
        int j = r * 256 + tid;
        (&Xs[0][0])[j] = X[(size_t)b * 16 * 256 + j];
    }

    float acc[4] = {0.f, 0.f, 0.f, 0.f};
    for (int c0 = 0; c0 < 256; c0 += 64) {
        __syncthreads();
#pragma unroll
        for (int r = 0; r < 16; ++r) {
            int j = r * 256 + tid;
            int dr = j >> 6, ccol = j & 63;
            Ws[dr][ccol] = W[(size_t)(d0 + dr) * 256 + c0 + ccol];
        }
        __syncthreads();
#pragma unroll 16
        for (int c = 0; c < 64; ++c) {
            float w = Ws[dl][c];
            acc[0] += Xs[kq + 0][c0 + c] * w;
            acc[1] += Xs[kq + 4][c0 + c] * w;
            acc[2] += Xs[kq + 8][c0 + c] * w;
            acc[3] += Xs[kq + 12][c0 + c] * w;
        }
    }

    const int d = d0 + dl;
    float s = 1.f, t = 0.f;
    if (MODE == 0) {
        s = g[d] * rsqrtf(vv[d] + EPSBN);
        t = bb[d] - mm[d] * s;
    }
#pragma unroll
    for (int r = 0; r < 4; ++r) {
        int k = kq + r * 4;
        float o = (MODE == 0) ? fmaxf(acc[r] * s + t, 0.f) : acc[r];
        Out[(size_t)(b * 16 + k) * 256 + d] = o;
    }
}

// ------------------------------ launcher -----------------------------------
extern "C" void kernel_launch(void* const* d_in, const int* in_sizes, int n_in,
                              void* d_out, int out_size) {
    const float* F   = (const float*)d_in[0];
    const float* xyz = (const float*)d_in[1];
    const float* W1  = (const float*)d_in[2];
    const float* g1  = (const float*)d_in[3];
    const float* b1  = (const float*)d_in[4];
    const float* m1  = (const float*)d_in[5];
    const float* v1  = (const float*)d_in[6];
    const float* W2  = (const float*)d_in[7];
    const float* g2  = (const float*)d_in[8];
    const float* b2  = (const float*)d_in[9];
    const float* m2  = (const float*)d_in[10];
    const float* v2  = (const float*)d_in[11];
    const float* W3  = (const float*)d_in[12];
    const float* g3  = (const float*)d_in[13];
    const float* b3  = (const float*)d_in[14];
    const float* m3  = (const float*)d_in[15];
    const float* v3  = (const float*)d_in[16];
    const float* Wo  = (const float*)d_in[17];
    const float* bo  = (const float*)d_in[18];
    const float* Wm1 = (const float*)d_in[19];
    const float* gm1 = (const float*)d_in[20];
    const float* bm1 = (const float*)d_in[21];
    const float* mm1 = (const float*)d_in[22];
    const float* vm1 = (const float*)d_in[23];
    const float* Wm2 = (const float*)d_in[24];
    const float* gm2 = (const float*)d_in[25];
    const float* bm2 = (const float*)d_in[26];
    const float* mm2 = (const float*)d_in[27];
    const float* vm2 = (const float*)d_in[28];
    const float* Wm3 = (const float*)d_in[29];
    float* out = (float*)d_out;

    float *x1, *x2, *x3, *off, *e, *sxyz, *kpp, *spart, *S, *fpart, *kpf, *y1, *y2;
    cudaGetSymbolAddress((void**)&x1, g_x1);
    cudaGetSymbolAddress((void**)&x2, g_x2);
    cudaGetSymbolAddress((void**)&x3, g_x3);
    cudaGetSymbolAddress((void**)&off, g_off);
    cudaGetSymbolAddress((void**)&e, g_e);
    cudaGetSymbolAddress((void**)&sxyz, g_sumxyz);
    cudaGetSymbolAddress((void**)&kpp, g_kpp);
    cudaGetSymbolAddress((void**)&spart, g_spart);
    cudaGetSymbolAddress((void**)&S, g_S);
    cudaGetSymbolAddress((void**)&fpart, g_fpart);
    cudaGetSymbolAddress((void**)&kpf, g_kpf);
    cudaGetSymbolAddress((void**)&y1, g_y1);
    cudaGetSymbolAddress((void**)&y2, g_y2);

    constexpr int SM128 = 2 * (128 + 128) * TSTR * 4;   // 81920 B
    constexpr int SM64  = 2 * (128 + 64)  * TSTR * 4;   // 61440 B

    cudaFuncSetAttribute(mma_gemm<0, 128>, cudaFuncAttributeMaxDynamicSharedMemorySize, SM128);
    cudaFuncSetAttribute(mma_gemm<1, 64>,  cudaFuncAttributeMaxDynamicSharedMemorySize, SM64);

    // backbone GEMM chain on bf16x3 tensor cores (BN+ReLU / bias fused)
    mma_gemm<0, 128><<<dim3(Mtot / 128, 2), 256, SM128>>>(F,  W1, g1, b1, m1, v1, x1, Mtot, 256, 256);
    mma_gemm<0, 128><<<dim3(Mtot / 128, 2), 256, SM128>>>(x1, W2, g2, b2, m2, v2, x2, Mtot, 256, 256);
    mma_gemm<0, 128><<<dim3(Mtot / 128, 4), 256, SM128>>>(x2, W3, g3, b3, m3, v3, x3, Mtot, 256, 512);
    mma_gemm<1, 64><<<dim3(Mtot / 128, 1), 256, SM64>>>(x3, Wo, bo, nullptr, nullptr, nullptr,
                                                        off, Mtot, 512, 48);
    // keypoint positions (deterministic mean)
    sumxyz_kernel<<<Bc, 256>>>(xyz, sxyz);
    kppos_kernel<<<Bc * Kc, 256>>>(off, sxyz, kpp, out);
    // softmax weights
    expdist_kernel<<<Bc * 64, 256>>>(xyz, off, kpp, e, spart);
    sreduce_kernel<<<1, 128>>>(spart, S);
    // weighted feature pooling
    kpfeat_partial_kernel<<<dim3(16, 4, Bc), 256>>>(F, e, fpart);
    kpfeat_reduce_kernel<<<Bc * Kc, 256>>>(fpart, S, kpf);
    // keypoint MLP (fp32 — tiny, keeps precision headroom)
    mlp_kernel<0><<<dim3(4, Bc), 256>>>(kpf, Wm1, gm1, bm1, mm1, vm1, y1);
    mlp_kernel<0><<<dim3(4, Bc), 256>>>(y1, Wm2, gm2, bm2, mm2, vm2, y2);
    mlp_kernel<1><<<dim3(4, Bc), 256>>>(y2, Wm3, nullptr, nullptr, nullptr, nullptr,
                                        out + Bc * Kc * 3);
}

// round 10
// speedup vs baseline: 2.1410x; 1.0404x over previous
#include <cuda_runtime.h>
#include <cstdint>

// ---------------------------------------------------------------------------
// InstanceAdaptiveKeypointDetector2 — bf16x3 mma.sync backbone + fp32 tail.
// R9 -> R10: splits hoisted out of the mainloop. Loader LDGs fp32, splits
// once (hi=bf16rn(a), lo=bf16rn(a-hi)), stores packed bf16 hi/lo tiles.
// Mainloop is pure LDS.32 + HMMA (zero cvt/sub). Register-staged double
// buffering: compute(ch) | split+STS(ch+1) | LDG(ch+2) | bar.
// B=8, N=16384, C=256, K=16.  Output = [kp_pos (8,16,3) | y (8,16,256)].
// ---------------------------------------------------------------------------

static constexpr int Bc   = 8;
static constexpr int Nn   = 16384;
static constexpr int Kc   = 16;
static constexpr int Mtot = Bc * Nn;          // 131072
#define EPSBN 1e-5f

// ------------------------------ scratch ------------------------------------
__device__ __align__(256) float g_x1[(size_t)Mtot * 256];
__device__ __align__(256) float g_x2[(size_t)Mtot * 256];
__device__ __align__(256) float g_x3[(size_t)Mtot * 512];
__device__ __align__(256) float g_off[(size_t)Mtot * 48];
__device__ __align__(256) float g_e[(size_t)Mtot * 16];
__device__ __align__(256) float g_sumxyz[Bc * 3];
__device__ __align__(256) float g_kpp[Bc * Kc * 3];
__device__ __align__(256) float g_spart[Bc * 64 * 16];
__device__ __align__(256) float g_S[Bc * Kc];
__device__ __align__(256) float g_fpart[(size_t)Bc * 4 * 16 * 16 * 64];
__device__ __align__(256) float g_kpf[Bc * Kc * 256];
__device__ __align__(256) float g_y1[Bc * Kc * 256];
__device__ __align__(256) float g_y2[Bc * Kc * 256];

// ------------------------------- helpers -----------------------------------
// bf16 m16n8k16 mma, fp32 accumulate
__device__ __forceinline__ void mma_bf16(float* c, const uint32_t* a, const uint32_t* b) {
    asm volatile(
        "mma.sync.aligned.m16n8k16.row.col.f32.bf16.bf16.f32 "
        "{%0,%1,%2,%3}, {%4,%5,%6,%7}, {%8,%9}, {%0,%1,%2,%3};"
        : "+f"(c[0]), "+f"(c[1]), "+f"(c[2]), "+f"(c[3])
        : "r"(a[0]), "r"(a[1]), "r"(a[2]), "r"(a[3]), "r"(b[0]), "r"(b[1]));
}

// split consecutive fp32 pair (x = even k, y = odd k) into bf16x2 hi + residual lo
__device__ __forceinline__ void split_bf(float x, float y, uint32_t& hi, uint32_t& lo) {
    asm("cvt.rn.bf16x2.f32 %0, %1, %2;" : "=r"(hi) : "f"(y), "f"(x));
    float h0 = __uint_as_float(hi << 16);
    float h1 = __uint_as_float(hi & 0xFFFF0000u);
    asm("cvt.rn.bf16x2.f32 %0, %1, %2;" : "=r"(lo) : "f"(y - h1), "f"(x - h0));
}

// ----------------------- bf16x3 tensor-core GEMM ---------------------------
// C[m][d] = epilogue( sum_k A[m][k] * W[d][k] )
// A: M x Kd row-major.  W: D x Kd row-major.  C: M x D row-major.
// Block tile 128 x NT, chunk = 16 K, 8 warps (2 x 4), warp tile 64 x NT/4.
// smem per stage: [Ahi | Alo | Bhi | Blo], bf16x2 words, row stride 12 words
// (8 data + 4 pad -> fragment LDS gq*12+tq distinct mod 32: conflict-free).
// MODE 0: relu(z*sc + tt), BN folded.  MODE 1: z + bias, d<D guards.
static constexpr int WSTR = 12;                  // words per 16-K row

template <int MODE, int NT>
__global__ __launch_bounds__(256, 2) void mma_gemm(
    const float* __restrict__ A, const float* __restrict__ W,
    const float* __restrict__ P0, const float* __restrict__ P1,
    const float* __restrict__ P2, const float* __restrict__ P3,
    float* __restrict__ C, int M, int Kd, int D)
{
    constexpr int NTW    = NT / 4;               // warp n-tile
    constexpr int NTC    = NT / 32;              // 8-wide nt iterations
    constexpr int NB4    = NT / 64;              // B float4 loads per thread
    constexpr int TILE_A = 128 * WSTR;           // words
    constexpr int TILE_B = NT * WSTR;
    constexpr int STAGEW = 2 * (TILE_A + TILE_B);

    extern __shared__ __align__(16) uint32_t smw[];

    const int tid  = threadIdx.x;
    const int wid  = tid >> 5, lane = tid & 31;
    const int wm   = wid & 1;          // 2 warp rows
    const int wn   = wid >> 1;         // 4 warp cols
    const int gq   = lane >> 2;        // group id 0..7
    const int tq   = lane & 3;         // thread-in-group 0..3
    const int m0   = blockIdx.x * 128;
    const int d0   = blockIdx.y * NT;

    const float* Ap = A + (size_t)m0 * Kd;
    const int nch = Kd / 16;

    // loader mapping: float4 j -> row r = j>>2, quad q = j&3
    const int lr = tid >> 2, lq = tid & 3;

    float4 ra[2], rb[NB4];
    auto ldg = [&](int ch) {
        const int k0 = ch * 16;
#pragma unroll
        for (int i = 0; i < 2; ++i)
            ra[i] = *reinterpret_cast<const float4*>(Ap + (size_t)(lr + i * 64) * Kd + k0 + lq * 4);
#pragma unroll
        for (int i = 0; i < NB4; ++i) {
            const int row = d0 + lr + i * 64;
            if (MODE == 0 || row < D)
                rb[i] = *reinterpret_cast<const float4*>(W + (size_t)row * Kd + k0 + lq * 4);
            else
                rb[i] = make_float4(0.f, 0.f, 0.f, 0.f);
        }
    };
    auto sts = [&](int buf) {
        uint32_t* base = smw + buf * STAGEW;
#pragma unroll
        for (int i = 0; i < 2; ++i) {
            uint32_t h0, l0, h1, l1;
            split_bf(ra[i].x, ra[i].y, h0, l0);
            split_bf(ra[i].z, ra[i].w, h1, l1);
            const int r = lr + i * 64;
            *reinterpret_cast<uint2*>(base + r * WSTR + 2 * lq)          = make_uint2(h0, h1);
            *reinterpret_cast<uint2*>(base + TILE_A + r * WSTR + 2 * lq) = make_uint2(l0, l1);
        }
        uint32_t* bb = base + 2 * TILE_A;
#pragma unroll
        for (int i = 0; i < NB4; ++i) {
            uint32_t h0, l0, h1, l1;
            split_bf(rb[i].x, rb[i].y, h0, l0);
            split_bf(rb[i].z, rb[i].w, h1, l1);
            const int r = lr + i * 64;
            *reinterpret_cast<uint2*>(bb + r * WSTR + 2 * lq)          = make_uint2(h0, h1);
            *reinterpret_cast<uint2*>(bb + TILE_B + r * WSTR + 2 * lq) = make_uint2(l0, l1);
        }
    };

    float acc[4][NTC][4];
#pragma unroll
    for (int mt = 0; mt < 4; ++mt)
#pragma unroll
        for (int nt = 0; nt < NTC; ++nt)
#pragma unroll
            for (int q = 0; q < 4; ++q) acc[mt][nt][q] = 0.f;

    ldg(0); sts(0); ldg(1);
    __syncthreads();

    for (int ch = 0; ch < nch; ++ch) {
        // ---------------- compute chunk ch (pure LDS + HMMA) --------------
        {
            const uint32_t* Ah = smw + (ch & 1) * STAGEW;
            const uint32_t* Al = Ah + TILE_A;
            const uint32_t* Bh = Ah + 2 * TILE_A;
            const uint32_t* Bl = Bh + TILE_B;

            uint32_t bh[NTC][2], bl[NTC][2];
#pragma unroll
            for (int nt = 0; nt < NTC; ++nt) {
                const int n = wn * NTW + nt * 8 + gq;
                bh[nt][0] = Bh[n * WSTR + tq];
                bh[nt][1] = Bh[n * WSTR + tq + 4];
                bl[nt][0] = Bl[n * WSTR + tq];
                bl[nt][1] = Bl[n * WSTR + tq + 4];
            }
#pragma unroll
            for (int mt = 0; mt < 4; ++mt) {
                const int r = wm * 64 + mt * 16 + gq;
                uint32_t ah[4], al[4];
                ah[0] = Ah[r * WSTR + tq];       ah[1] = Ah[(r + 8) * WSTR + tq];
                ah[2] = Ah[r * WSTR + tq + 4];   ah[3] = Ah[(r + 8) * WSTR + tq + 4];
                al[0] = Al[r * WSTR + tq];       al[1] = Al[(r + 8) * WSTR + tq];
                al[2] = Al[r * WSTR + tq + 4];   al[3] = Al[(r + 8) * WSTR + tq + 4];
#pragma unroll
                for (int nt = 0; nt < NTC; ++nt) {
                    mma_bf16(acc[mt][nt], ah, bh[nt]);   // main
                    mma_bf16(acc[mt][nt], al, bh[nt]);   // A residual
                    mma_bf16(acc[mt][nt], ah, bl[nt]);   // B residual
                }
            }
        }
        // ------------- stage ch+1 into smem, prefetch ch+2 -----------------
        if (ch + 1 < nch) sts((ch + 1) & 1);
        if (ch + 2 < nch) ldg(ch + 2);
        __syncthreads();
    }

    // ------------------------------ epilogue -------------------------------
    // BN fold computed here (keeps mainloop register pressure low)
#pragma unroll
    for (int nt = 0; nt < NTC; ++nt) {
        float sc[2], tt[2];
#pragma unroll
        for (int j = 0; j < 2; ++j) {
            const int d = d0 + wn * NTW + nt * 8 + 2 * tq + j;
            if (MODE == 0) {
                float s = P0[d] * rsqrtf(P3[d] + EPSBN);
                sc[j] = s;
                tt[j] = P1[d] - P2[d] * s;
            } else {
                sc[j] = 1.f;
                tt[j] = (d < D) ? P0[d] : 0.f;
            }
        }
#pragma unroll
        for (int mt = 0; mt < 4; ++mt) {
            const int m = m0 + wm * 64 + mt * 16 + gq;
            const int d = d0 + wn * NTW + nt * 8 + 2 * tq;
            float v0 = acc[mt][nt][0] * sc[0] + tt[0];
            float v1 = acc[mt][nt][1] * sc[1] + tt[1];
            float v2 = acc[mt][nt][2] * sc[0] + tt[0];
            float v3 = acc[mt][nt][3] * sc[1] + tt[1];
            if (MODE == 0) {
                v0 = fmaxf(v0, 0.f); v1 = fmaxf(v1, 0.f);
                v2 = fmaxf(v2, 0.f); v3 = fmaxf(v3, 0.f);
            }
            if (MODE == 0 || d < D) {
                *reinterpret_cast<float2*>(C + (size_t)m * D + d)       = make_float2(v0, v1);
                *reinterpret_cast<float2*>(C + (size_t)(m + 8) * D + d) = make_float2(v2, v3);
            }
        }
    }
}

// ------------------------- sum of xyz over points --------------------------
__global__ void sumxyz_kernel(const float* __restrict__ xyz, float* __restrict__ out) {
    const int b = blockIdx.x;
    const int tid = threadIdx.x;
    __shared__ float red[256][4];
    float s0 = 0.f, s1 = 0.f, s2 = 0.f;
    const float* p = xyz + (size_t)b * Nn * 3;
    for (int n = tid; n < Nn; n += 256) {
        s0 += p[n * 3 + 0];
        s1 += p[n * 3 + 1];
        s2 += p[n * 3 + 2];
    }
    red[tid][0] = s0; red[tid][1] = s1; red[tid][2] = s2;
    __syncthreads();
    for (int st = 128; st > 0; st >>= 1) {
        if (tid < st) {
            red[tid][0] += red[tid + st][0];
            red[tid][1] += red[tid + st][1];
            red[tid][2] += red[tid + st][2];
        }
        __syncthreads();
    }
    if (tid < 3) out[b * 3 + tid] = red[0][tid];
}

// ------------------------------ kp_pos -------------------------------------
__global__ void kppos_kernel(const float* __restrict__ off, const float* __restrict__ sxyz,
                             float* __restrict__ kpp, float* __restrict__ outp) {
    const int b = blockIdx.x >> 4;
    const int k = blockIdx.x & 15;
    const int tid = threadIdx.x;
    __shared__ float red[256][4];
    float s0 = 0.f, s1 = 0.f, s2 = 0.f;
    const float* p = off + (size_t)b * Nn * 48 + k * 3;
    for (int n = tid; n < Nn; n += 256) {
        size_t base = (size_t)n * 48;
        s0 += p[base + 0];
        s1 += p[base + 1];
        s2 += p[base + 2];
    }
    red[tid][0] = s0; red[tid][1] = s1; red[tid][2] = s2;
    __syncthreads();
    for (int st = 128; st > 0; st >>= 1) {
        if (tid < st) {
            red[tid][0] += red[tid + st][0];
            red[tid][1] += red[tid + st][1];
            red[tid][2] += red[tid + st][2];
        }
        __syncthreads();
    }
    if (tid < 3) {
        float v = (red[0][tid] + sxyz[b * 3 + tid]) * (1.f / (float)Nn);
        kpp[b * 48 + k * 3 + tid]  = v;
        outp[b * 48 + k * 3 + tid] = v;   // kp_pos is the first output
    }
}

// -------------------- exp(-dist) + per-block partial sums ------------------
__global__ __launch_bounds__(256) void expdist_kernel(
    const float* __restrict__ xyz, const float* __restrict__ off,
    const float* __restrict__ kpp, float* __restrict__ Eo, float* __restrict__ Spart)
{
    const int b = blockIdx.x >> 6;
    const int chunk = blockIdx.x & 63;
    const int tid = threadIdx.x;
    const int n = chunk * 256 + tid;
    const size_t gid = (size_t)b * Nn + n;

    __shared__ float kps[48];
    __shared__ float eS[256][17];
    if (tid < 48) kps[tid] = kpp[b * 48 + tid];
    __syncthreads();

    float4 ob4[12];
    const float4* op = reinterpret_cast<const float4*>(off + gid * 48);
#pragma unroll
    for (int i = 0; i < 12; ++i) ob4[i] = op[i];
    const float* ob = reinterpret_cast<const float*>(ob4);

    const float px = xyz[gid * 3 + 0];
    const float py = xyz[gid * 3 + 1];
    const float pz = xyz[gid * 3 + 2];

    float4 eb4[4];
    float* eb = reinterpret_cast<float*>(eb4);
#pragma unroll
    for (int k = 0; k < 16; ++k) {
        float vx = px + ob[3 * k + 0] - kps[3 * k + 0];
        float vy = py + ob[3 * k + 1] - kps[3 * k + 1];
        float vz = pz + ob[3 * k + 2] - kps[3 * k + 2];
        float e = expf(-sqrtf(vx * vx + vy * vy + vz * vz));
        eb[k] = e;
        eS[tid][k] = e;
    }
    float4* ew = reinterpret_cast<float4*>(Eo + gid * 16);
#pragma unroll
    for (int i = 0; i < 4; ++i) ew[i] = eb4[i];

    __syncthreads();
    for (int st = 128; st > 0; st >>= 1) {
        if (tid < st) {
#pragma unroll
            for (int k = 0; k < 16; ++k) eS[tid][k] += eS[tid + st][k];
        }
        __syncthreads();
    }
    if (tid < 16) Spart[(size_t)(b * 64 + chunk) * 16 + tid] = eS[0][tid];
}

// ------------------------ softmax denominators -----------------------------
__global__ void sreduce_kernel(const float* __restrict__ Spart, float* __restrict__ S) {
    const int t = threadIdx.x;          // 128 threads = (b,k)
    const int b = t >> 4, k = t & 15;
    float s = 0.f;
    for (int c = 0; c < 64; ++c) s += Spart[(size_t)(b * 64 + c) * 16 + k];
    S[t] = s;
}

// ------------------- keypoint feature pooling (partial) --------------------
__global__ __launch_bounds__(256) void kpfeat_partial_kernel(
    const float* __restrict__ F, const float* __restrict__ E, float* __restrict__ P)
{
    const int slab = blockIdx.x;   // 16 slabs of 1024 points
    const int cc   = blockIdx.y;   // 4 chunks of 64 channels
    const int b    = blockIdx.z;
    const int tid  = threadIdx.x;
    const int cl = tid & 63, kg = tid >> 6;

    __shared__ float Fs[16][64];
    __shared__ float es[16][17];
    float a0 = 0.f, a1 = 0.f, a2 = 0.f, a3 = 0.f;
    const int nbase = slab * 1024;

    for (int c0 = 0; c0 < 1024; c0 += 16) {
        __syncthreads();
#pragma unroll
        for (int r = 0; r < 4; ++r) {
            int j = r * 256 + tid;
            int nn = j >> 6, c = j & 63;
            Fs[nn][c] = F[(size_t)(b * Nn + nbase + c0 + nn) * 256 + cc * 64 + c];
        }
        {
            int nn = tid >> 4, kk = tid & 15;
            es[nn][kk] = E[(size_t)(b * Nn + nbase + c0 + nn) * 16 + kk];
        }
        __syncthreads();
#pragma unroll
        for (int nn = 0; nn < 16; ++nn) {
            float f = Fs[nn][cl];
            a0 += f * es[nn][kg * 4 + 0];
            a1 += f * es[nn][kg * 4 + 1];
            a2 += f * es[nn][kg * 4 + 2];
            a3 += f * es[nn][kg * 4 + 3];
        }
    }
    size_t base = ((size_t)(b * 4 + cc) * 16 + slab) * 16 * 64;
    P[base + (size_t)(kg * 4 + 0) * 64 + cl] = a0;
    P[base + (size_t)(kg * 4 + 1) * 64 + cl] = a1;
    P[base + (size_t)(kg * 4 + 2) * 64 + cl] = a2;
    P[base + (size_t)(kg * 4 + 3) * 64 + cl] = a3;
}

__global__ void kpfeat_reduce_kernel(const float* __restrict__ P, const float* __restrict__ S,
                                     float* __restrict__ KF) {
    const int b = blockIdx.x >> 4, k = blockIdx.x & 15;
    const int c = threadIdx.x;
    const int cc = c >> 6, cl = c & 63;
    float s = 0.f;
    for (int slab = 0; slab < 16; ++slab)
        s += P[(((size_t)(b * 4 + cc) * 16 + slab) * 16 + k) * 64 + cl];
    KF[(size_t)(b * 16 + k) * 256 + c] = s / S[b * 16 + k];
}

// ---------------------------- keypoint MLP ---------------------------------
// MODE 0: relu(bn(X @ W^T)).  MODE 1: plain X @ W^T (no bias).
template <int MODE>
__global__ __launch_bounds__(256) void mlp_kernel(
    const float* __restrict__ X, const float* __restrict__ W,
    const float* __restrict__ g, const float* __restrict__ bb,
    const float* __restrict__ mm, const float* __restrict__ vv,
    float* __restrict__ Out)
{
    const int d0 = blockIdx.x * 64;
    const int b  = blockIdx.y;
    const int tid = threadIdx.x;
    const int dl = tid & 63, kq = tid >> 6;

    __shared__ float Xs[16][256];
    __shared__ float Ws[64][65];

#pragma unroll
    for (int r = 0; r < 16; ++r) {
        int j = r * 256 + tid;
        (&Xs[0][0])[j] = X[(size_t)b * 16 * 256 + j];
    }

    float acc[4] = {0.f, 0.f, 0.f, 0.f};
    for (int c0 = 0; c0 < 256; c0 += 64) {
        __syncthreads();
#pragma unroll
        for (int r = 0; r < 16; ++r) {
            int j = r * 256 + tid;
            int dr = j >> 6, ccol = j & 63;
            Ws[dr][ccol] = W[(size_t)(d0 + dr) * 256 + c0 + ccol];
        }
        __syncthreads();
#pragma unroll 16
        for (int c = 0; c < 64; ++c) {
            float w = Ws[dl][c];
            acc[0] += Xs[kq + 0][c0 + c] * w;
            acc[1] += Xs[kq + 4][c0 + c] * w;
            acc[2] += Xs[kq + 8][c0 + c] * w;
            acc[3] += Xs[kq + 12][c0 + c] * w;
        }
    }

    const int d = d0 + dl;
    float s = 1.f, t = 0.f;
    if (MODE == 0) {
        s = g[d] * rsqrtf(vv[d] + EPSBN);
        t = bb[d] - mm[d] * s;
    }
#pragma unroll
    for (int r = 0; r < 4; ++r) {
        int k = kq + r * 4;
        float o = (MODE == 0) ? fmaxf(acc[r] * s + t, 0.f) : acc[r];
        Out[(size_t)(b * 16 + k) * 256 + d] = o;
    }
}

// ------------------------------ launcher -----------------------------------
extern "C" void kernel_launch(void* const* d_in, const int* in_sizes, int n_in,
                              void* d_out, int out_size) {
    const float* F   = (const float*)d_in[0];
    const float* xyz = (const float*)d_in[1];
    const float* W1  = (const float*)d_in[2];
    const float* g1  = (const float*)d_in[3];
    const float* b1  = (const float*)d_in[4];
    const float* m1  = (const float*)d_in[5];
    const float* v1  = (const float*)d_in[6];
    const float* W2  = (const float*)d_in[7];
    const float* g2  = (const float*)d_in[8];
    const float* b2  = (const float*)d_in[9];
    const float* m2  = (const float*)d_in[10];
    const float* v2  = (const float*)d_in[11];
    const float* W3  = (const float*)d_in[12];
    const float* g3  = (const float*)d_in[13];
    const float* b3  = (const float*)d_in[14];
    const float* m3  = (const float*)d_in[15];
    const float* v3  = (const float*)d_in[16];
    const float* Wo  = (const float*)d_in[17];
    const float* bo  = (const float*)d_in[18];
    const float* Wm1 = (const float*)d_in[19];
    const float* gm1 = (const float*)d_in[20];
    const float* bm1 = (const float*)d_in[21];
    const float* mm1 = (const float*)d_in[22];
    const float* vm1 = (const float*)d_in[23];
    const float* Wm2 = (const float*)d_in[24];
    const float* gm2 = (const float*)d_in[25];
    const float* bm2 = (const float*)d_in[26];
    const float* mm2 = (const float*)d_in[27];
    const float* vm2 = (const float*)d_in[28];
    const float* Wm3 = (const float*)d_in[29];
    float* out = (float*)d_out;

    float *x1, *x2, *x3, *off, *e, *sxyz, *kpp, *spart, *S, *fpart, *kpf, *y1, *y2;
    cudaGetSymbolAddress((void**)&x1, g_x1);
    cudaGetSymbolAddress((void**)&x2, g_x2);
    cudaGetSymbolAddress((void**)&x3, g_x3);
    cudaGetSymbolAddress((void**)&off, g_off);
    cudaGetSymbolAddress((void**)&e, g_e);
    cudaGetSymbolAddress((void**)&sxyz, g_sumxyz);
    cudaGetSymbolAddress((void**)&kpp, g_kpp);
    cudaGetSymbolAddress((void**)&spart, g_spart);
    cudaGetSymbolAddress((void**)&S, g_S);
    cudaGetSymbolAddress((void**)&fpart, g_fpart);
    cudaGetSymbolAddress((void**)&kpf, g_kpf);
    cudaGetSymbolAddress((void**)&y1, g_y1);
    cudaGetSymbolAddress((void**)&y2, g_y2);

    // smem: 2 stages x 2(hi,lo) x (128+NT) rows x 12 words x 4B
    constexpr int SM128 = 2 * 2 * (128 + 128) * WSTR * 4;   // 49152 B
    constexpr int SM64  = 2 * 2 * (128 + 64)  * WSTR * 4;   // 36864 B

    cudaFuncSetAttribute(mma_gemm<0, 128>, cudaFuncAttributeMaxDynamicSharedMemorySize, SM128);
    cudaFuncSetAttribute(mma_gemm<1, 64>,  cudaFuncAttributeMaxDynamicSharedMemorySize, SM64);

    // backbone GEMM chain on bf16x3 tensor cores (BN+ReLU / bias fused)
    mma_gemm<0, 128><<<dim3(Mtot / 128, 2), 256, SM128>>>(F,  W1, g1, b1, m1, v1, x1, Mtot, 256, 256);
    mma_gemm<0, 128><<<dim3(Mtot / 128, 2), 256, SM128>>>(x1, W2, g2, b2, m2, v2, x2, Mtot, 256, 256);
    mma_gemm<0, 128><<<dim3(Mtot / 128, 4), 256, SM128>>>(x2, W3, g3, b3, m3, v3, x3, Mtot, 256, 512);
    mma_gemm<1, 64><<<dim3(Mtot / 128, 1), 256, SM64>>>(x3, Wo, bo, nullptr, nullptr, nullptr,
                                                        off, Mtot, 512, 48);
    // keypoint positions (deterministic mean)
    sumxyz_kernel<<<Bc, 256>>>(xyz, sxyz);
    kppos_kernel<<<Bc * Kc, 256>>>(off, sxyz, kpp, out);
    // softmax weights
    expdist_kernel<<<Bc * 64, 256>>>(xyz, off, kpp, e, spart);
    sreduce_kernel<<<1, 128>>>(spart, S);
    // weighted feature pooling
    kpfeat_partial_kernel<<<dim3(16, 4, Bc), 256>>>(F, e, fpart);
    kpfeat_reduce_kernel<<<Bc * Kc, 256>>>(fpart, S, kpf);
    // keypoint MLP (fp32 — tiny, keeps precision headroom)
    mlp_kernel<0><<<dim3(4, Bc), 256>>>(kpf, Wm1, gm1, bm1, mm1, vm1, y1);
    mlp_kernel<0><<<dim3(4, Bc), 256>>>(y1, Wm2, gm2, bm2, mm2, vm2, y2);
    mlp_kernel<1><<<dim3(4, Bc), 256>>>(y2, Wm3, nullptr, nullptr, nullptr, nullptr,
                                        out + Bc * Kc * 3);
}

// round 13
// speedup vs baseline: 2.3900x; 1.1163x over previous
#include <cuda_runtime.h>
#include <cstdint>

// ---------------------------------------------------------------------------
// InstanceAdaptiveKeypointDetector2 — bf16x3 mma.sync backbone + fp32 tail.
// R10 -> R11: fragment loads switched from 48x LDS.32 to 12x ldmatrix.x4 per
// warp-chunk (layout already conflict-free for LDSM at WSTR=12). Mainloop is
// LDSM + HMMA only; loader still LDG fp32 -> split once -> STS packed bf16.
// B=8, N=16384, C=256, K=16.  Output = [kp_pos (8,16,3) | y (8,16,256)].
// ---------------------------------------------------------------------------

static constexpr int Bc   = 8;
static constexpr int Nn   = 16384;
static constexpr int Kc   = 16;
static constexpr int Mtot = Bc * Nn;          // 131072
#define EPSBN 1e-5f

// ------------------------------ scratch ------------------------------------
__device__ __align__(256) float g_x1[(size_t)Mtot * 256];
__device__ __align__(256) float g_x2[(size_t)Mtot * 256];
__device__ __align__(256) float g_x3[(size_t)Mtot * 512];
__device__ __align__(256) float g_off[(size_t)Mtot * 48];
__device__ __align__(256) float g_e[(size_t)Mtot * 16];
__device__ __align__(256) float g_sumxyz[Bc * 3];
__device__ __align__(256) float g_kpp[Bc * Kc * 3];
__device__ __align__(256) float g_spart[Bc * 64 * 16];
__device__ __align__(256) float g_S[Bc * Kc];
__device__ __align__(256) float g_fpart[(size_t)Bc * 4 * 16 * 16 * 64];
__device__ __align__(256) float g_kpf[Bc * Kc * 256];
__device__ __align__(256) float g_y1[Bc * Kc * 256];
__device__ __align__(256) float g_y2[Bc * Kc * 256];

// ------------------------------- helpers -----------------------------------
__device__ __forceinline__ uint32_t smem_u32(const void* p) {
    uint32_t a;
    asm("{ .reg .u64 t; cvta.to.shared.u64 t, %1; cvt.u32.u64 %0, t; }"
        : "=r"(a) : "l"(p));
    return a;
}

// bf16 m16n8k16 mma, fp32 accumulate
__device__ __forceinline__ void mma_bf16(float* c, const uint32_t* a, const uint32_t* b) {
    asm volatile(
        "mma.sync.aligned.m16n8k16.row.col.f32.bf16.bf16.f32 "
        "{%0,%1,%2,%3}, {%4,%5,%6,%7}, {%8,%9}, {%0,%1,%2,%3};"
        : "+f"(c[0]), "+f"(c[1]), "+f"(c[2]), "+f"(c[3])
        : "r"(a[0]), "r"(a[1]), "r"(a[2]), "r"(a[3]), "r"(b[0]), "r"(b[1]));
}

// ldmatrix x4 (non-transposed), b16
__device__ __forceinline__ void ldsm4(uint32_t* r, uint32_t addr) {
    asm volatile("ldmatrix.sync.aligned.m8n8.x4.shared.b16 {%0,%1,%2,%3}, [%4];"
                 : "=r"(r[0]), "=r"(r[1]), "=r"(r[2]), "=r"(r[3]) : "r"(addr));
}

// split consecutive fp32 pair (x = even k, y = odd k) into bf16x2 hi + residual lo
__device__ __forceinline__ void split_bf(float x, float y, uint32_t& hi, uint32_t& lo) {
    asm("cvt.rn.bf16x2.f32 %0, %1, %2;" : "=r"(hi) : "f"(y), "f"(x));
    float h0 = __uint_as_float(hi << 16);
    float h1 = __uint_as_float(hi & 0xFFFF0000u);
    asm("cvt.rn.bf16x2.f32 %0, %1, %2;" : "=r"(lo) : "f"(y - h1), "f"(x - h0));
}

// ----------------------- bf16x3 tensor-core GEMM ---------------------------
// C[m][d] = epilogue( sum_k A[m][k] * W[d][k] )
// A: M x Kd row-major.  W: D x Kd row-major.  C: M x D row-major.
// Block tile 128 x NT, chunk = 16 K, 8 warps (2 x 4), warp tile 64 x NT/4.
// smem stage: [Ahi | Alo | Bhi | Blo]; bf16x2 words, row = 8 data words
// (halves at +0 / +4) + 4 pad -> stride 12: 8-row LDSM groups hit 16B bank
// groups {0,12,24,4,16,28,8,20} mod 32 = conflict-free.
// MODE 0: relu(z*sc + tt), BN folded.  MODE 1: z + bias, d<D guards.
static constexpr int WSTR = 12;                  // words per 16-K row

template <int MODE, int NT>
__global__ __launch_bounds__(256, 2) void mma_gemm(
    const float* __restrict__ A, const float* __restrict__ W,
    const float* __restrict__ P0, const float* __restrict__ P1,
    const float* __restrict__ P2, const float* __restrict__ P3,
    float* __restrict__ C, int M, int Kd, int D)
{
    constexpr int NTW    = NT / 4;               // warp n-tile
    constexpr int NTC    = NT / 32;              // 8-wide nt iterations
    constexpr int NPAIR  = NTC / 2;              // ldmatrix B pair groups
    constexpr int NB4    = NT / 64;              // B float4 loads per thread
    constexpr int TILE_A = 128 * WSTR;           // words
    constexpr int TILE_B = NT * WSTR;
    constexpr int STAGEW = 2 * (TILE_A + TILE_B);

    extern __shared__ __align__(16) uint32_t smw[];
    const uint32_t smb = smem_u32(smw);

    const int tid  = threadIdx.x;
    const int wid  = tid >> 5, lane = tid & 31;
    const int wm   = wid & 1;          // 2 warp rows
    const int wn   = wid >> 1;         // 4 warp cols
    const int gq   = lane >> 2;        // group id 0..7
    const int tq   = lane & 3;         // thread-in-group 0..3
    const int m0   = blockIdx.x * 128;
    const int d0   = blockIdx.y * NT;

    // per-lane ldmatrix address offsets (bytes)
    const int q2 = lane >> 3, rr = lane & 7;
    const uint32_t aOff = (uint32_t)(((wm * 64 + (q2 & 1) * 8 + rr) * WSTR + (q2 >> 1) * 4) * 4);
    const uint32_t bOff = (uint32_t)(((wn * NTW + (q2 >> 1) * 8 + rr) * WSTR + (q2 & 1) * 4) * 4);

    const float* Ap = A + (size_t)m0 * Kd;
    const int nch = Kd / 16;

    // loader mapping: float4 j -> row r = j>>2, quad q = j&3
    const int lr = tid >> 2, lq = tid & 3;

    float4 ra[2], rb[NB4];
    auto ldg = [&](int ch) {
        const int k0 = ch * 16;
#pragma unroll
        for (int i = 0; i < 2; ++i)
            ra[i] = *reinterpret_cast<const float4*>(Ap + (size_t)(lr + i * 64) * Kd + k0 + lq * 4);
#pragma unroll
        for (int i = 0; i < NB4; ++i) {
            const int row = d0 + lr + i * 64;
            if (MODE == 0 || row < D)
                rb[i] = *reinterpret_cast<const float4*>(W + (size_t)row * Kd + k0 + lq * 4);
            else
                rb[i] = make_float4(0.f, 0.f, 0.f, 0.f);
        }
    };
    auto sts = [&](int buf) {
        uint32_t* base = smw + buf * STAGEW;
#pragma unroll
        for (int i = 0; i < 2; ++i) {
            uint32_t h0, l0, h1, l1;
            split_bf(ra[i].x, ra[i].y, h0, l0);
            split_bf(ra[i].z, ra[i].w, h1, l1);
            const int r = lr + i * 64;
            *reinterpret_cast<uint2*>(base + r * WSTR + 2 * lq)          = make_uint2(h0, h1);
            *reinterpret_cast<uint2*>(base + TILE_A + r * WSTR + 2 * lq) = make_uint2(l0, l1);
        }
        uint32_t* bb = base + 2 * TILE_A;
#pragma unroll
        for (int i = 0; i < NB4; ++i) {
            uint32_t h0, l0, h1, l1;
            split_bf(rb[i].x, rb[i].y, h0, l0);
            split_bf(rb[i].z, rb[i].w, h1, l1);
            const int r = lr + i * 64;
            *reinterpret_cast<uint2*>(bb + r * WSTR + 2 * lq)          = make_uint2(h0, h1);
            *reinterpret_cast<uint2*>(bb + TILE_B + r * WSTR + 2 * lq) = make_uint2(l0, l1);
        }
    };

    float acc[4][NTC][4];
#pragma unroll
    for (int mt = 0; mt < 4; ++mt)
#pragma unroll
        for (int nt = 0; nt < NTC; ++nt)
#pragma unroll
            for (int q = 0; q < 4; ++q) acc[mt][nt][q] = 0.f;

    ldg(0); sts(0); ldg(1);
    __syncthreads();

    for (int ch = 0; ch < nch; ++ch) {
        // ---------------- compute chunk ch (LDSM + HMMA only) --------------
        {
            const uint32_t sAh = smb + (uint32_t)((ch & 1) * STAGEW) * 4u;
            const uint32_t sAl = sAh + (uint32_t)TILE_A * 4u;
            const uint32_t sBh = sAh + (uint32_t)(2 * TILE_A) * 4u;
            const uint32_t sBl = sBh + (uint32_t)TILE_B * 4u;

            // B fragments: one ldmatrix.x4 covers two nt groups (n16 x k16)
            uint32_t bh4[NPAIR][4], bl4[NPAIR][4];
#pragma unroll
            for (int p = 0; p < NPAIR; ++p) {
                const uint32_t po = (uint32_t)(p * 16 * WSTR * 4);
                ldsm4(bh4[p], sBh + bOff + po);
                ldsm4(bl4[p], sBl + bOff + po);
            }
#pragma unroll
            for (int mt = 0; mt < 4; ++mt) {
                const uint32_t mo = (uint32_t)(mt * 16 * WSTR * 4);
                uint32_t ah[4], al[4];
                ldsm4(ah, sAh + aOff + mo);
                ldsm4(al, sAl + aOff + mo);
#pragma unroll
                for (int nt = 0; nt < NTC; ++nt) {
                    const uint32_t* bh = &bh4[nt >> 1][(nt & 1) * 2];
                    const uint32_t* bl = &bl4[nt >> 1][(nt & 1) * 2];
                    mma_bf16(acc[mt][nt], ah, bh);   // main
                    mma_bf16(acc[mt][nt], al, bh);   // A residual
                    mma_bf16(acc[mt][nt], ah, bl);   // B residual
                }
            }
        }
        // ------------- stage ch+1 into smem, prefetch ch+2 -----------------
        if (ch + 1 < nch) sts((ch + 1) & 1);
        if (ch + 2 < nch) ldg(ch + 2);
        __syncthreads();
    }

    // ------------------------------ epilogue -------------------------------
#pragma unroll
    for (int nt = 0; nt < NTC; ++nt) {
        float sc[2], tt[2];
#pragma unroll
        for (int j = 0; j < 2; ++j) {
            const int d = d0 + wn * NTW + nt * 8 + 2 * tq + j;
            if (MODE == 0) {
                float s = P0[d] * rsqrtf(P3[d] + EPSBN);
                sc[j] = s;
                tt[j] = P1[d] - P2[d] * s;
            } else {
                sc[j] = 1.f;
                tt[j] = (d < D) ? P0[d] : 0.f;
            }
        }
#pragma unroll
        for (int mt = 0; mt < 4; ++mt) {
            const int m = m0 + wm * 64 + mt * 16 + gq;
            const int d = d0 + wn * NTW + nt * 8 + 2 * tq;
            float v0 = acc[mt][nt][0] * sc[0] + tt[0];
            float v1 = acc[mt][nt][1] * sc[1] + tt[1];
            float v2 = acc[mt][nt][2] * sc[0] + tt[0];
            float v3 = acc[mt][nt][3] * sc[1] + tt[1];
            if (MODE == 0) {
                v0 = fmaxf(v0, 0.f); v1 = fmaxf(v1, 0.f);
                v2 = fmaxf(v2, 0.f); v3 = fmaxf(v3, 0.f);
            }
            if (MODE == 0 || d < D) {
                *reinterpret_cast<float2*>(C + (size_t)m * D + d)       = make_float2(v0, v1);
                *reinterpret_cast<float2*>(C + (size_t)(m + 8) * D + d) = make_float2(v2, v3);
            }
        }
    }
}

// ------------------------- sum of xyz over points --------------------------
__global__ void sumxyz_kernel(const float* __restrict__ xyz, float* __restrict__ out) {
    const int b = blockIdx.x;
    const int tid = threadIdx.x;
    __shared__ float red[256][4];
    float s0 = 0.f, s1 = 0.f, s2 = 0.f;
    const float* p = xyz + (size_t)b * Nn * 3;
    for (int n = tid; n < Nn; n += 256) {
        s0 += p[n * 3 + 0];
        s1 += p[n * 3 + 1];
        s2 += p[n * 3 + 2];
    }
    red[tid][0] = s0; red[tid][1] = s1; red[tid][2] = s2;
    __syncthreads();
    for (int st = 128; st > 0; st >>= 1) {
        if (tid < st) {
            red[tid][0] += red[tid + st][0];
            red[tid][1] += red[tid + st][1];
            red[tid][2] += red[tid + st][2];
        }
        __syncthreads();
    }
    if (tid < 3) out[b * 3 + tid] = red[0][tid];
}

// ------------------------------ kp_pos -------------------------------------
__global__ void kppos_kernel(const float* __restrict__ off, const float* __restrict__ sxyz,
                             float* __restrict__ kpp, float* __restrict__ outp) {
    const int b = blockIdx.x >> 4;
    const int k = blockIdx.x & 15;
    const int tid = threadIdx.x;
    __shared__ float red[256][4];
    float s0 = 0.f, s1 = 0.f, s2 = 0.f;
    const float* p = off + (size_t)b * Nn * 48 + k * 3;
    for (int n = tid; n < Nn; n += 256) {
        size_t base = (size_t)n * 48;
        s0 += p[base + 0];
        s1 += p[base + 1];
        s2 += p[base + 2];
    }
    red[tid][0] = s0; red[tid][1] = s1; red[tid][2] = s2;
    __syncthreads();
    for (int st = 128; st > 0; st >>= 1) {
        if (tid < st) {
            red[tid][0] += red[tid + st][0];
            red[tid][1] += red[tid + st][1];
            red[tid][2] += red[tid + st][2];
        }
        __syncthreads();
    }
    if (tid < 3) {
        float v = (red[0][tid] + sxyz[b * 3 + tid]) * (1.f / (float)Nn);
        kpp[b * 48 + k * 3 + tid]  = v;
        outp[b * 48 + k * 3 + tid] = v;   // kp_pos is the first output
    }
}

// -------------------- exp(-dist) + per-block partial sums ------------------
__global__ __launch_bounds__(256) void expdist_kernel(
    const float* __restrict__ xyz, const float* __restrict__ off,
    const float* __restrict__ kpp, float* __restrict__ Eo, float* __restrict__ Spart)
{
    const int b = blockIdx.x >> 6;
    const int chunk = blockIdx.x & 63;
    const int tid = threadIdx.x;
    const int n = chunk * 256 + tid;
    const size_t gid = (size_t)b * Nn + n;

    __shared__ float kps[48];
    __shared__ float eS[256][17];
    if (tid < 48) kps[tid] = kpp[b * 48 + tid];
    __syncthreads();

    float4 ob4[12];
    const float4* op = reinterpret_cast<const float4*>(off + gid * 48);
#pragma unroll
    for (int i = 0; i < 12; ++i) ob4[i] = op[i];
    const float* ob = reinterpret_cast<const float*>(ob4);

    const float px = xyz[gid * 3 + 0];
    const float py = xyz[gid * 3 + 1];
    const float pz = xyz[gid * 3 + 2];

    float4 eb4[4];
    float* eb = reinterpret_cast<float*>(eb4);
#pragma unroll
    for (int k = 0; k < 16; ++k) {
        float vx = px + ob[3 * k + 0] - kps[3 * k + 0];
        float vy = py + ob[3 * k + 1] - kps[3 * k + 1];
        float vz = pz + ob[3 * k + 2] - kps[3 * k + 2];
        float e = expf(-sqrtf(vx * vx + vy * vy + vz * vz));
        eb[k] = e;
        eS[tid][k] = e;
    }
    float4* ew = reinterpret_cast<float4*>(Eo + gid * 16);
#pragma unroll
    for (int i = 0; i < 4; ++i) ew[i] = eb4[i];

    __syncthreads();
    for (int st = 128; st > 0; st >>= 1) {
        if (tid < st) {
#pragma unroll
            for (int k = 0; k < 16; ++k) eS[tid][k] += eS[tid + st][k];
        }
        __syncthreads();
    }
    if (tid < 16) Spart[(size_t)(b * 64 + chunk) * 16 + tid] = eS[0][tid];
}

// ------------------------ softmax denominators -----------------------------
__global__ void sreduce_kernel(const float* __restrict__ Spart, float* __restrict__ S) {
    const int t = threadIdx.x;          // 128 threads = (b,k)
    const int b = t >> 4, k = t & 15;
    float s = 0.f;
    for (int c = 0; c < 64; ++c) s += Spart[(size_t)(b * 64 + c) * 16 + k];
    S[t] = s;
}

// ------------------- keypoint feature pooling (partial) --------------------
__global__ __launch_bounds__(256) void kpfeat_partial_kernel(
    const float* __restrict__ F, const float* __restrict__ E, float* __restrict__ P)
{
    const int slab = blockIdx.x;   // 16 slabs of 1024 points
    const int cc   = blockIdx.y;   // 4 chunks of 64 channels
    const int b    = blockIdx.z;
    const int tid  = threadIdx.x;
    const int cl = tid & 63, kg = tid >> 6;

    __shared__ float Fs[16][64];
    __shared__ float es[16][17];
    float a0 = 0.f, a1 = 0.f, a2 = 0.f, a3 = 0.f;
    const int nbase = slab * 1024;

    for (int c0 = 0; c0 < 1024; c0 += 16) {
        __syncthreads();
#pragma unroll
        for (int r = 0; r < 4; ++r) {
            int j = r * 256 + tid;
            int nn = j >> 6, c = j & 63;
            Fs[nn][c] = F[(size_t)(b * Nn + nbase + c0 + nn) * 256 + cc * 64 + c];
        }
        {
            int nn = tid >> 4, kk = tid & 15;
            es[nn][kk] = E[(size_t)(b * Nn + nbase + c0 + nn) * 16 + kk];
        }
        __syncthreads();
#pragma unroll
        for (int nn = 0; nn < 16; ++nn) {
            float f = Fs[nn][cl];
            a0 += f * es[nn][kg * 4 + 0];
            a1 += f * es[nn][kg * 4 + 1];
            a2 += f * es[nn][kg * 4 + 2];
            a3 += f * es[nn][kg * 4 + 3];
        }
    }
    size_t base = ((size_t)(b * 4 + cc) * 16 + slab) * 16 * 64;
    P[base + (size_t)(kg * 4 + 0) * 64 + cl] = a0;
    P[base + (size_t)(kg * 4 + 1) * 64 + cl] = a1;
    P[base + (size_t)(kg * 4 + 2) * 64 + cl] = a2;
    P[base + (size_t)(kg * 4 + 3) * 64 + cl] = a3;
}

__global__ void kpfeat_reduce_kernel(const float* __restrict__ P, const float* __restrict__ S,
                                     float* __restrict__ KF) {
    const int b = blockIdx.x >> 4, k = blockIdx.x & 15;
    const int c = threadIdx.x;
    const int cc = c >> 6, cl = c & 63;
    float s = 0.f;
    for (int slab = 0; slab < 16; ++slab)
        s += P[(((size_t)(b * 4 + cc) * 16 + slab) * 16 + k) * 64 + cl];
    KF[(size_t)(b * 16 + k) * 256 + c] = s / S[b * 16 + k];
}

// ---------------------------- keypoint MLP ---------------------------------
// MODE 0: relu(bn(X @ W^T)).  MODE 1: plain X @ W^T (no bias).
template <int MODE>
__global__ __launch_bounds__(256) void mlp_kernel(
    const float* __restrict__ X, const float* __restrict__ W,
    const float* __restrict__ g, const float* __restrict__ bb,
    const float* __restrict__ mm, const float* __restrict__ vv,
    float* __restrict__ Out)
{
    const int d0 = blockIdx.x * 64;
    const int b  = blockIdx.y;
    const int tid = threadIdx.x;
    const int dl = tid & 63, kq = tid >> 6;

    __shared__ float Xs[16][256];
    __shared__ float Ws[64][65];

#pragma unroll
    for (int r = 0; r < 16; ++r) {
        int j = r * 256 + tid;
        (&Xs[0][0])[j] = X[(size_t)b * 16 * 256 + j];
    }

    float acc[4] = {0.f, 0.f, 0.f, 0.f};
    for (int c0 = 0; c0 < 256; c0 += 64) {
        __syncthreads();
#pragma unroll
        for (int r = 0; r < 16; ++r) {
            int j = r * 256 + tid;
            int dr = j >> 6, ccol = j & 63;
            Ws[dr][ccol] = W[(size_t)(d0 + dr) * 256 + c0 + ccol];
        }
        __syncthreads();
#pragma unroll 16
        for (int c = 0; c < 64; ++c) {
            float w = Ws[dl][c];
            acc[0] += Xs[kq + 0][c0 + c] * w;
            acc[1] += Xs[kq + 4][c0 + c] * w;
            acc[2] += Xs[kq + 8][c0 + c] * w;
            acc[3] += Xs[kq + 12][c0 + c] * w;
        }
    }

    const int d = d0 + dl;
    float s = 1.f, t = 0.f;
    if (MODE == 0) {
        s = g[d] * rsqrtf(vv[d] + EPSBN);
        t = bb[d] - mm[d] * s;
    }
#pragma unroll
    for (int r = 0; r < 4; ++r) {
        int k = kq + r * 4;
        float o = (MODE == 0) ? fmaxf(acc[r] * s + t, 0.f) : acc[r];
        Out[(size_t)(b * 16 + k) * 256 + d] = o;
    }
}

// ------------------------------ launcher -----------------------------------
extern "C" void kernel_launch(void* const* d_in, const int* in_sizes, int n_in,
                              void* d_out, int out_size) {
    const float* F   = (const float*)d_in[0];
    const float* xyz = (const float*)d_in[1];
    const float* W1  = (const float*)d_in[2];
    const float* g1  = (const float*)d_in[3];
    const float* b1  = (const float*)d_in[4];
    const float* m1  = (const float*)d_in[5];
    const float* v1  = (const float*)d_in[6];
    const float* W2  = (const float*)d_in[7];
    const float* g2  = (const float*)d_in[8];
    const float* b2  = (const float*)d_in[9];
    const float* m2  = (const float*)d_in[10];
    const float* v2  = (const float*)d_in[11];
    const float* W3  = (const float*)d_in[12];
    const float* g3  = (const float*)d_in[13];
    const float* b3  = (const float*)d_in[14];
    const float* m3  = (const float*)d_in[15];
    const float* v3  = (const float*)d_in[16];
    const float* Wo  = (const float*)d_in[17];
    const float* bo  = (const float*)d_in[18];
    const float* Wm1 = (const float*)d_in[19];
    const float* gm1 = (const float*)d_in[20];
    const float* bm1 = (const float*)d_in[21];
    const float* mm1 = (const float*)d_in[22];
    const float* vm1 = (const float*)d_in[23];
    const float* Wm2 = (const float*)d_in[24];
    const float* gm2 = (const float*)d_in[25];
    const float* bm2 = (const float*)d_in[26];
    const float* mm2 = (const float*)d_in[27];
    const float* vm2 = (const float*)d_in[28];
    const float* Wm3 = (const float*)d_in[29];
    float* out = (float*)d_out;

    float *x1, *x2, *x3, *off, *e, *sxyz, *kpp, *spart, *S, *fpart, *kpf, *y1, *y2;
    cudaGetSymbolAddress((void**)&x1, g_x1);
    cudaGetSymbolAddress((void**)&x2, g_x2);
    cudaGetSymbolAddress((void**)&x3, g_x3);
    cudaGetSymbolAddress((void**)&off, g_off);
    cudaGetSymbolAddress((void**)&e, g_e);
    cudaGetSymbolAddress((void**)&sxyz, g_sumxyz);
    cudaGetSymbolAddress((void**)&kpp, g_kpp);
    cudaGetSymbolAddress((void**)&spart, g_spart);
    cudaGetSymbolAddress((void**)&S, g_S);
    cudaGetSymbolAddress((void**)&fpart, g_fpart);
    cudaGetSymbolAddress((void**)&kpf, g_kpf);
    cudaGetSymbolAddress((void**)&y1, g_y1);
    cudaGetSymbolAddress((void**)&y2, g_y2);

    // smem: 2 stages x 2(hi,lo) x (128+NT) rows x 12 words x 4B
    constexpr int SM128 = 2 * 2 * (128 + 128) * WSTR * 4;   // 49152 B
    constexpr int SM64  = 2 * 2 * (128 + 64)  * WSTR * 4;   // 36864 B

    cudaFuncSetAttribute(mma_gemm<0, 128>, cudaFuncAttributeMaxDynamicSharedMemorySize, SM128);
    cudaFuncSetAttribute(mma_gemm<1, 64>,  cudaFuncAttributeMaxDynamicSharedMemorySize, SM64);

    // backbone GEMM chain on bf16x3 tensor cores (BN+ReLU / bias fused)
    mma_gemm<0, 128><<<dim3(Mtot / 128, 2), 256, SM128>>>(F,  W1, g1, b1, m1, v1, x1, Mtot, 256, 256);
    mma_gemm<0, 128><<<dim3(Mtot / 128, 2), 256, SM128>>>(x1, W2, g2, b2, m2, v2, x2, Mtot, 256, 256);
    mma_gemm<0, 128><<<dim3(Mtot / 128, 4), 256, SM128>>>(x2, W3, g3, b3, m3, v3, x3, Mtot, 256, 512);
    mma_gemm<1, 64><<<dim3(Mtot / 128, 1), 256, SM64>>>(x3, Wo, bo, nullptr, nullptr, nullptr,
                                                        off, Mtot, 512, 48);
    // keypoint positions (deterministic mean)
    sumxyz_kernel<<<Bc, 256>>>(xyz, sxyz);
    kppos_kernel<<<Bc * Kc, 256>>>(off, sxyz, kpp, out);
    // softmax weights
    expdist_kernel<<<Bc * 64, 256>>>(xyz, off, kpp, e, spart);
    sreduce_kernel<<<1, 128>>>(spart, S);
    // weighted feature pooling
    kpfeat_partial_kernel<<<dim3(16, 4, Bc), 256>>>(F, e, fpart);
    kpfeat_reduce_kernel<<<Bc * Kc, 256>>>(fpart, S, kpf);
    // keypoint MLP (fp32 — tiny, keeps precision headroom)
    mlp_kernel<0><<<dim3(4, Bc), 256>>>(kpf, Wm1, gm1, bm1, mm1, vm1, y1);
    mlp_kernel<0><<<dim3(4, Bc), 256>>>(y1, Wm2, gm2, bm2, mm2, vm2, y2);
    mlp_kernel<1><<<dim3(4, Bc), 256>>>(y2, Wm3, nullptr, nullptr, nullptr, nullptr,
                                        out + Bc * Kc * 3);
}